// round 1
// baseline (speedup 1.0000x reference)
#include <cuda_runtime.h>
#include <cstdint>

// ---------------------------------------------------------------------------
// CFConv: out[a,f] = sum_nb x[neighbors[a,nb], f] * W[a,nb,f]
//   h = softplus(rbf @ w1 + b1)   [N,32,128]
//   W = h @ w2 + b2               [N,32,128]
// N=20000, NB=32, R=64, F=128 (derived from in_sizes at runtime)
// ---------------------------------------------------------------------------

#define F_DIM 128
#define R_DIM 64
#define NB_DIM 32
#define ATOMS_PER_BLOCK 16
#define N_THREADS 256
#define N_WARPS (N_THREADS / 32)

struct Smem {
    float w1[R_DIM][F_DIM];      // 32 KB
    float w2[F_DIM][F_DIM];      // 64 KB
    float b1[F_DIM];
    float b2[F_DIM];
    float rbf[NB_DIM][R_DIM];    // 8 KB, per-atom staging
    float h[NB_DIM][F_DIM];      // 16 KB
    float psum[N_WARPS][F_DIM];  // 4 KB
};
#define SMEM_BYTES ((int)sizeof(Smem))

__device__ int g_idx64_flag;

// Detect whether the neighbors buffer is int64 (little-endian: every odd
// 32-bit word of the first 2048 words would be zero since values < 2^31) or
// int32 (odd words are random neighbor indices; all-zero is impossible in
// practice). Deterministic for fixed inputs.
__global__ void detect_idx64_kernel(const int* __restrict__ nb_raw) {
    __shared__ int nonzero;
    if (threadIdx.x == 0) nonzero = 0;
    __syncthreads();
    int local = 0;
    for (int i = threadIdx.x; i < 1024; i += blockDim.x)
        local |= nb_raw[2 * i + 1];
    if (local) atomicOr(&nonzero, 1);
    __syncthreads();
    if (threadIdx.x == 0) g_idx64_flag = (nonzero == 0) ? 1 : 0;
}

__device__ __forceinline__ float softplus_f(float z) {
    // stable: max(z,0) + log1p(exp(-|z|))  == log1p(exp(z))
    return fmaxf(z, 0.0f) + log1pf(expf(-fabsf(z)));
}

__global__ __launch_bounds__(N_THREADS, 1)
void cfconv_kernel(const float* __restrict__ x,
                   const float* __restrict__ rbf_g,
                   const void*  __restrict__ nbr_raw,
                   const float* __restrict__ w1,
                   const float* __restrict__ b1,
                   const float* __restrict__ w2,
                   const float* __restrict__ b2,
                   float* __restrict__ out,
                   int n_atoms)
{
    extern __shared__ char smem_raw[];
    Smem& s = *reinterpret_cast<Smem*>(smem_raw);
    const int t = threadIdx.x;
    const bool idx64 = (g_idx64_flag != 0);

    // ---- stage weights/biases in SMEM (amortized over 16 atoms) ----
    {
        const float4* w1g = reinterpret_cast<const float4*>(w1);
        float4* w1s = reinterpret_cast<float4*>(&s.w1[0][0]);
        #pragma unroll
        for (int i = 0; i < (R_DIM * F_DIM / 4) / N_THREADS; ++i)   // 8
            w1s[t + i * N_THREADS] = w1g[t + i * N_THREADS];
        const float4* w2g = reinterpret_cast<const float4*>(w2);
        float4* w2s = reinterpret_cast<float4*>(&s.w2[0][0]);
        #pragma unroll
        for (int i = 0; i < (F_DIM * F_DIM / 4) / N_THREADS; ++i)   // 16
            w2s[t + i * N_THREADS] = w2g[t + i * N_THREADS];
        if (t < F_DIM) { s.b1[t] = b1[t]; s.b2[t] = b2[t]; }
    }
    __syncthreads();

    // thread tile: 4 neighbors x 4 features
    const int fg  = t & 31;     // feature group within warp
    const int wid = t >> 5;     // warp id = neighbor group
    const int f0  = fg * 4;
    const int nb0 = wid * 4;

    const int a_begin = blockIdx.x * ATOMS_PER_BLOCK;
    const int a_end   = min(a_begin + ATOMS_PER_BLOCK, n_atoms);

    for (int a = a_begin; a < a_end; ++a) {
        // ---- stage rbf[a] : 32x64 floats (coalesced float4) ----
        {
            const float4* rg = reinterpret_cast<const float4*>(
                rbf_g + (size_t)a * (NB_DIM * R_DIM));
            float4* rs = reinterpret_cast<float4*>(&s.rbf[0][0]);
            rs[t]             = rg[t];
            rs[t + N_THREADS] = rg[t + N_THREADS];
        }
        __syncthreads();

        // ---- GEMM1: h = softplus(rbf @ w1 + b1) ----
        float acc[4][4];
        {
            const float4 bv = *reinterpret_cast<const float4*>(&s.b1[f0]);
            #pragma unroll
            for (int i = 0; i < 4; ++i) {
                acc[i][0] = bv.x; acc[i][1] = bv.y;
                acc[i][2] = bv.z; acc[i][3] = bv.w;
            }
            #pragma unroll 8
            for (int r = 0; r < R_DIM; ++r) {
                const float4 w = *reinterpret_cast<const float4*>(&s.w1[r][f0]);
                #pragma unroll
                for (int i = 0; i < 4; ++i) {
                    const float rv = s.rbf[nb0 + i][r];   // warp-uniform broadcast
                    acc[i][0] = fmaf(rv, w.x, acc[i][0]);
                    acc[i][1] = fmaf(rv, w.y, acc[i][1]);
                    acc[i][2] = fmaf(rv, w.z, acc[i][2]);
                    acc[i][3] = fmaf(rv, w.w, acc[i][3]);
                }
            }
            #pragma unroll
            for (int i = 0; i < 4; ++i) {
                float4 hv;
                hv.x = softplus_f(acc[i][0]);
                hv.y = softplus_f(acc[i][1]);
                hv.z = softplus_f(acc[i][2]);
                hv.w = softplus_f(acc[i][3]);
                *reinterpret_cast<float4*>(&s.h[nb0 + i][f0]) = hv;
            }
        }
        __syncthreads();

        // ---- gather x_j early (latency hidden under GEMM2 K-loop) ----
        float4 xj[4];
        if (idx64) {
            const long long* nb = reinterpret_cast<const long long*>(nbr_raw)
                                  + (size_t)a * NB_DIM + nb0;
            #pragma unroll
            for (int i = 0; i < 4; ++i) {
                const long long j = nb[i];
                xj[i] = *reinterpret_cast<const float4*>(x + (size_t)j * F_DIM + f0);
            }
        } else {
            const int* nb = reinterpret_cast<const int*>(nbr_raw)
                            + (size_t)a * NB_DIM + nb0;
            #pragma unroll
            for (int i = 0; i < 4; ++i) {
                const int j = nb[i];
                xj[i] = *reinterpret_cast<const float4*>(x + (size_t)j * F_DIM + f0);
            }
        }

        // ---- GEMM2: W = h @ w2 + b2 ----
        float wa[4][4];
        {
            const float4 bv = *reinterpret_cast<const float4*>(&s.b2[f0]);
            #pragma unroll
            for (int i = 0; i < 4; ++i) {
                wa[i][0] = bv.x; wa[i][1] = bv.y;
                wa[i][2] = bv.z; wa[i][3] = bv.w;
            }
            #pragma unroll 8
            for (int g = 0; g < F_DIM; ++g) {
                const float4 w = *reinterpret_cast<const float4*>(&s.w2[g][f0]);
                #pragma unroll
                for (int i = 0; i < 4; ++i) {
                    const float hv = s.h[nb0 + i][g];     // warp-uniform broadcast
                    wa[i][0] = fmaf(hv, w.x, wa[i][0]);
                    wa[i][1] = fmaf(hv, w.y, wa[i][1]);
                    wa[i][2] = fmaf(hv, w.z, wa[i][2]);
                    wa[i][3] = fmaf(hv, w.w, wa[i][3]);
                }
            }
        }

        // ---- combine with gathered x_j; per-warp partial over its 4 nb ----
        {
            float4 p;
            p.x = xj[0].x * wa[0][0] + xj[1].x * wa[1][0]
                + xj[2].x * wa[2][0] + xj[3].x * wa[3][0];
            p.y = xj[0].y * wa[0][1] + xj[1].y * wa[1][1]
                + xj[2].y * wa[2][1] + xj[3].y * wa[3][1];
            p.z = xj[0].z * wa[0][2] + xj[1].z * wa[1][2]
                + xj[2].z * wa[2][2] + xj[3].z * wa[3][2];
            p.w = xj[0].w * wa[0][3] + xj[1].w * wa[1][3]
                + xj[2].w * wa[2][3] + xj[3].w * wa[3][3];
            *reinterpret_cast<float4*>(&s.psum[wid][f0]) = p;
        }
        __syncthreads();

        // ---- reduce 8 warp-partials, coalesced 512B row store ----
        if (t < F_DIM) {
            float v = 0.0f;
            #pragma unroll
            for (int k = 0; k < N_WARPS; ++k) v += s.psum[k][t];
            out[(size_t)a * F_DIM + t] = v;
        }
        __syncthreads();   // protect rbf/h/psum before next atom
    }
}

extern "C" void kernel_launch(void* const* d_in, const int* in_sizes, int n_in,
                              void* d_out, int out_size)
{
    const float* x    = (const float*)d_in[0];
    const float* rbf  = (const float*)d_in[1];
    const void*  nbrs = d_in[2];
    const float* w1   = (const float*)d_in[3];
    const float* b1   = (const float*)d_in[4];
    const float* w2   = (const float*)d_in[5];
    const float* b2   = (const float*)d_in[6];
    float* out = (float*)d_out;

    const int n_atoms = in_sizes[0] / F_DIM;

    cudaFuncSetAttribute(cfconv_kernel,
                         cudaFuncAttributeMaxDynamicSharedMemorySize, SMEM_BYTES);

    detect_idx64_kernel<<<1, 256>>>((const int*)nbrs);

    const int grid = (n_atoms + ATOMS_PER_BLOCK - 1) / ATOMS_PER_BLOCK;
    cfconv_kernel<<<grid, N_THREADS, SMEM_BYTES>>>(
        x, rbf, nbrs, w1, b1, w2, b2, out, n_atoms);
}

// round 3
// speedup vs baseline: 2.4981x; 2.4981x over previous
#include <cuda_runtime.h>
#include <cuda_bf16.h>
#include <cstdint>

// ===========================================================================
// CFConv via mma.sync (HMMA, bf16, m16n8k16) with 3-pass bf16 split.
//   Tile = 4 atoms (M=128 rows = 4 x 32 nb, N=128 feats), 2 tiles / CTA.
//   GEMM1: D1[128,128] = rbf[128,64] @ w1[64,128]
//   GEMM2: D2[128,128] = softplus(D1+b1)[128,128] @ w2[128,128]
//   out[a,f] = sum_nb x[nbr[a,nb],f] * (D2[nb,f] + b2[f])
// No tcgen05 (ptxas target is base sm_103).
// ===========================================================================

#define N_THREADS 256
#define ATOMS_PER_CTA 8
#define F_DIM 128

// padded element strides (odd multiples of 8 -> conflict-free ldmatrix)
#define S1 72    // K=64 tiles
#define S2 136   // K=128 tiles

// ---- smem byte offsets ----
#define SM_B1H 0
#define SM_B1L (SM_B1H + 128*S1*2)      // 18432
#define SM_B2H (SM_B1L + 128*S1*2)      // 36864
#define SM_B2L (SM_B2H + 128*S2*2)      // 71680
#define SM_A1H (SM_B2L + 128*S2*2)      // 106496
#define SM_A1L (SM_A1H + 128*S1*2)      // 124928
#define SM_HH  (SM_A1L + 128*S1*2)      // 143360
#define SM_HL  (SM_HH  + 128*S2*2)      // 178176
#define SM_BS1 (SM_HL  + 128*S2*2)      // 212992
#define SM_BS2 (SM_BS1 + 512)
#define SMEM_BYTES (SM_BS2 + 512)       // 214016

#define WIMG_BYTES (4*128*S1*2 /*B1 h+l*/ + 0) // computed below properly
__device__ __align__(16) unsigned char g_wimg[128*S1*2*2 + 128*S2*2*2]; // 106496
__device__ int g_idx64_flag;

// ---------------------------------------------------------------------------
__device__ __forceinline__ uint32_t smem_u32(const void* p) {
    uint32_t a;
    asm("{ .reg .u64 t; cvta.to.shared.u64 t, %1; cvt.u32.u64 %0, t; }" : "=r"(a) : "l"(p));
    return a;
}

__device__ __forceinline__ void ldsm4(uint32_t addr, uint32_t r[4]) {
    asm volatile("ldmatrix.sync.aligned.m8n8.x4.shared.b16 {%0,%1,%2,%3}, [%4];"
        : "=r"(r[0]), "=r"(r[1]), "=r"(r[2]), "=r"(r[3]) : "r"(addr));
}

__device__ __forceinline__ void mma16816(float c[4], const uint32_t a[4],
                                         uint32_t b0, uint32_t b1) {
    asm volatile("mma.sync.aligned.m16n8k16.row.col.f32.bf16.bf16.f32 "
        "{%0,%1,%2,%3}, {%4,%5,%6,%7}, {%8,%9}, {%0,%1,%2,%3};"
        : "+f"(c[0]), "+f"(c[1]), "+f"(c[2]), "+f"(c[3])
        : "r"(a[0]), "r"(a[1]), "r"(a[2]), "r"(a[3]), "r"(b0), "r"(b1));
}

__device__ __forceinline__ void split_bf16(float v, uint16_t& h, uint16_t& l) {
    __nv_bfloat16 hb = __float2bfloat16(v);
    __nv_bfloat16 lb = __float2bfloat16(v - __bfloat162float(hb));
    h = __bfloat16_as_ushort(hb);
    l = __bfloat16_as_ushort(lb);
}
__device__ __forceinline__ float softplus_fast(float z) {
    return fmaxf(z, 0.0f) + __logf(1.0f + __expf(-fabsf(z)));
}

// A: [128 rows][STRIDE k] bf16 hi/lo; B: [128 n][STRIDE k] bf16 hi/lo.
// Warp computes C[m0..m0+31][nb0..nb0+63], 3-pass split accumulate.
template<int KSTEPS, int STRIDE>
__device__ __forceinline__ void gemm_block(
    uint32_t aH, uint32_t aL, uint32_t bH, uint32_t bL,
    int m0, int nb0, int lane, float c[2][8][4])
{
    const uint32_t a_row = m0 + (lane & 15);
    const uint32_t a_k   = (lane >> 4) << 3;
    const uint32_t b_row = nb0 + ((lane >> 4) << 3) + (lane & 7);
    const uint32_t b_k   = ((lane >> 3) & 1) << 3;
    #pragma unroll
    for (int ks = 0; ks < KSTEPS; ++ks) {
        const uint32_t k0 = ks * 16;
        uint32_t ah[2][4], al[2][4];
        #pragma unroll
        for (int mi = 0; mi < 2; ++mi) {
            uint32_t off = ((a_row + mi * 16) * STRIDE + k0 + a_k) * 2;
            ldsm4(aH + off, ah[mi]);
            ldsm4(aL + off, al[mi]);
        }
        #pragma unroll
        for (int ng = 0; ng < 4; ++ng) {
            uint32_t boff = ((b_row + ng * 16) * STRIDE + k0 + b_k) * 2;
            uint32_t bh[4], bl[4];
            ldsm4(bH + boff, bh);
            ldsm4(bL + boff, bl);
            #pragma unroll
            for (int mi = 0; mi < 2; ++mi) {
                #pragma unroll
                for (int nj = 0; nj < 2; ++nj) {
                    mma16816(c[mi][ng * 2 + nj], ah[mi], bh[2*nj], bh[2*nj+1]);
                    mma16816(c[mi][ng * 2 + nj], ah[mi], bl[2*nj], bl[2*nj+1]);
                    mma16816(c[mi][ng * 2 + nj], al[mi], bh[2*nj], bh[2*nj+1]);
                }
            }
        }
    }
}

// ---------------------------------------------------------------------------
// prep: transpose + bf16-split weights into padded K-major images
//   B1[n=f][k=r] stride S1 ; B2[n=f][k=g] stride S2
// ---------------------------------------------------------------------------
__global__ void prep_weights(const float* __restrict__ w1, const float* __restrict__ w2) {
    uint16_t* b1h = (uint16_t*)(g_wimg);
    uint16_t* b1l = (uint16_t*)(g_wimg + 128*S1*2);
    uint16_t* b2h = (uint16_t*)(g_wimg + 128*S1*2*2);
    uint16_t* b2l = (uint16_t*)(g_wimg + 128*S1*2*2 + 128*S2*2);
    int stride = gridDim.x * blockDim.x;
    for (int idx = blockIdx.x * blockDim.x + threadIdx.x; idx < 64*128; idx += stride) {
        int r = idx >> 7, f = idx & 127;
        uint16_t h, l; split_bf16(w1[idx], h, l);
        b1h[f * S1 + r] = h;
        b1l[f * S1 + r] = l;
    }
    for (int idx = blockIdx.x * blockDim.x + threadIdx.x; idx < 128*128; idx += stride) {
        int g = idx >> 7, f = idx & 127;
        uint16_t h, l; split_bf16(w2[idx], h, l);
        b2h[f * S2 + g] = h;
        b2l[f * S2 + g] = l;
    }
}

// neighbors dtype detection (int64 vs int32), deterministic for fixed input
__global__ void detect_idx64_kernel(const int* __restrict__ nb_raw) {
    __shared__ int nonzero;
    if (threadIdx.x == 0) nonzero = 0;
    __syncthreads();
    int local = 0;
    for (int i = threadIdx.x; i < 1024; i += blockDim.x) local |= nb_raw[2 * i + 1];
    if (local) atomicOr(&nonzero, 1);
    __syncthreads();
    if (threadIdx.x == 0) g_idx64_flag = (nonzero == 0) ? 1 : 0;
}

// ---------------------------------------------------------------------------
__global__ __launch_bounds__(N_THREADS, 1)
void cfconv_mma(const float* __restrict__ x,
                const float* __restrict__ rbf,
                const void*  __restrict__ nbr,
                const float* __restrict__ b1,
                const float* __restrict__ b2,
                float* __restrict__ out,
                int n_atoms)
{
    extern __shared__ __align__(16) char smem[];
    const uint32_t sb = smem_u32(smem);
    const int t = threadIdx.x, wid = t >> 5, lane = t & 31;

    // weights image -> smem: 106496 B = 6656 float4 = 26 x 256
    {
        const float4* src = (const float4*)g_wimg;
        float4* dst = (float4*)smem;
        #pragma unroll
        for (int i = 0; i < 26; ++i) dst[t + i * N_THREADS] = src[t + i * N_THREADS];
    }
    if (t < F_DIM) {
        ((float*)(smem + SM_BS1))[t] = b1[t];
        ((float*)(smem + SM_BS2))[t] = b2[t];
    }
    __syncthreads();

    const int idxsh = g_idx64_flag;
    const int* nb32 = (const int*)nbr;
    const float* bs1 = (const float*)(smem + SM_BS1);
    const float* bs2 = (const float*)(smem + SM_BS2);

    const int m0  = (wid & 3) * 32;     // warp row block (= atom within tile)
    const int nb0 = (wid >> 2) * 64;    // warp col block
    const int qr  = lane >> 2;          // accum frag row within 8
    const int qc  = (lane & 3) * 2;     // accum frag col pair

    #pragma unroll 1
    for (int tile = 0; tile < ATOMS_PER_CTA / 4; ++tile) {
        const int abase = blockIdx.x * ATOMS_PER_CTA + tile * 4;

        // ---- stage rbf tile [128 rows][64 k] -> bf16 hi/lo, stride S1 ----
        {
            const float4* rg = (const float4*)rbf + (size_t)abase * 512;
            #pragma unroll
            for (int i = 0; i < 8; ++i) {
                int idx = t + i * N_THREADS;          // 0..2047
                int row = idx >> 4, c4 = (idx & 15) << 2;
                float4 v = make_float4(0.f, 0.f, 0.f, 0.f);
                if (abase + (row >> 5) < n_atoms) v = rg[idx];
                uint16_t h0,l0,h1,l1,h2,l2,h3,l3;
                split_bf16(v.x, h0, l0); split_bf16(v.y, h1, l1);
                split_bf16(v.z, h2, l2); split_bf16(v.w, h3, l3);
                uint32_t o = (uint32_t)(row * S1 + c4) * 2;
                *(uint2*)(smem + SM_A1H + o) =
                    make_uint2(((uint32_t)h1 << 16) | h0, ((uint32_t)h3 << 16) | h2);
                *(uint2*)(smem + SM_A1L + o) =
                    make_uint2(((uint32_t)l1 << 16) | l0, ((uint32_t)l3 << 16) | l2);
            }
        }
        __syncthreads();

        float c[2][8][4];

        // ---- GEMM1 ----
        #pragma unroll
        for (int mi = 0; mi < 2; ++mi)
            #pragma unroll
            for (int ng = 0; ng < 8; ++ng)
                c[mi][ng][0] = c[mi][ng][1] = c[mi][ng][2] = c[mi][ng][3] = 0.f;
        gemm_block<4, S1>(sb + SM_A1H, sb + SM_A1L, sb + SM_B1H, sb + SM_B1L,
                          m0, nb0, lane, c);

        // ---- softplus(D1 + b1) -> H (bf16 hi/lo, stride S2) ----
        #pragma unroll
        for (int mi = 0; mi < 2; ++mi) {
            #pragma unroll
            for (int ng = 0; ng < 8; ++ng) {
                const int cc = nb0 + ng * 8 + qc;
                const int r0 = m0 + mi * 16 + qr;
                float s0 = softplus_fast(c[mi][ng][0] + bs1[cc]);
                float s1 = softplus_fast(c[mi][ng][1] + bs1[cc + 1]);
                float s2 = softplus_fast(c[mi][ng][2] + bs1[cc]);
                float s3 = softplus_fast(c[mi][ng][3] + bs1[cc + 1]);
                uint16_t h0,l0,h1,l1,h2,l2,h3,l3;
                split_bf16(s0, h0, l0); split_bf16(s1, h1, l1);
                split_bf16(s2, h2, l2); split_bf16(s3, h3, l3);
                uint32_t oa = (uint32_t)(r0 * S2 + cc) * 2;
                uint32_t ob = (uint32_t)((r0 + 8) * S2 + cc) * 2;
                *(uint32_t*)(smem + SM_HH + oa) = ((uint32_t)h1 << 16) | h0;
                *(uint32_t*)(smem + SM_HL + oa) = ((uint32_t)l1 << 16) | l0;
                *(uint32_t*)(smem + SM_HH + ob) = ((uint32_t)h3 << 16) | h2;
                *(uint32_t*)(smem + SM_HL + ob) = ((uint32_t)l3 << 16) | l2;
            }
        }
        __syncthreads();

        // ---- GEMM2 ----
        #pragma unroll
        for (int mi = 0; mi < 2; ++mi)
            #pragma unroll
            for (int ng = 0; ng < 8; ++ng)
                c[mi][ng][0] = c[mi][ng][1] = c[mi][ng][2] = c[mi][ng][3] = 0.f;
        gemm_block<8, S2>(sb + SM_HH, sb + SM_HL, sb + SM_B2H, sb + SM_B2L,
                          m0, nb0, lane, c);
        __syncthreads();   // all warps done reading H before Wbuf overwrite

        // ---- epilogue: W = D2 + b2 -> warp-private smem; gather x; reduce ----
        {
            float* wb = (float*)(smem + SM_HH) + wid * (32 * 68);
            #pragma unroll
            for (int mi = 0; mi < 2; ++mi) {
                #pragma unroll
                for (int ng = 0; ng < 8; ++ng) {
                    const int cc = nb0 + ng * 8 + qc;     // global col
                    const int lc = ng * 8 + qc;           // warp-local col 0..63
                    const int r0 = mi * 16 + qr;          // local nb row
                    wb[r0 * 68 + lc]       = c[mi][ng][0] + bs2[cc];
                    wb[r0 * 68 + lc + 1]   = c[mi][ng][1] + bs2[cc + 1];
                    wb[(r0 + 8) * 68 + lc]     = c[mi][ng][2] + bs2[cc];
                    wb[(r0 + 8) * 68 + lc + 1] = c[mi][ng][3] + bs2[cc + 1];
                }
            }
            __syncwarp();

            const int atom = abase + (wid & 3);
            int j = 0;
            if (atom < n_atoms) j = nb32[((size_t)atom * 32 + lane) << idxsh];

            float acc0 = 0.f, acc1 = 0.f;
            const float* x0 = x + nb0 + lane;
            #pragma unroll 4
            for (int nb = 0; nb < 32; ++nb) {
                const int jn = __shfl_sync(0xffffffffu, j, nb);
                const float* xr = x0 + (size_t)jn * F_DIM;
                acc0 = fmaf(__ldg(xr),      wb[nb * 68 + lane],      acc0);
                acc1 = fmaf(__ldg(xr + 32), wb[nb * 68 + 32 + lane], acc1);
            }
            if (atom < n_atoms) {
                out[(size_t)atom * F_DIM + nb0 + lane]      = acc0;
                out[(size_t)atom * F_DIM + nb0 + 32 + lane] = acc1;
            }
        }
        __syncthreads();   // Wbuf (H region) + A1 reuse across tiles
    }
}

// ---------------------------------------------------------------------------
extern "C" void kernel_launch(void* const* d_in, const int* in_sizes, int n_in,
                              void* d_out, int out_size)
{
    const float* x    = (const float*)d_in[0];
    const float* rbf  = (const float*)d_in[1];
    const void*  nbrs = d_in[2];
    const float* w1   = (const float*)d_in[3];
    const float* b1   = (const float*)d_in[4];
    const float* w2   = (const float*)d_in[5];
    const float* b2   = (const float*)d_in[6];
    float* out = (float*)d_out;

    const int n_atoms = in_sizes[0] / F_DIM;

    cudaFuncSetAttribute(cfconv_mma,
                         cudaFuncAttributeMaxDynamicSharedMemorySize, SMEM_BYTES);

    detect_idx64_kernel<<<1, 256>>>((const int*)nbrs);
    prep_weights<<<64, 256>>>(w1, w2);

    const int grid = (n_atoms + ATOMS_PER_CTA - 1) / ATOMS_PER_CTA;
    cfconv_mma<<<grid, N_THREADS, SMEM_BYTES>>>(x, rbf, nbrs, b1, b2, out, n_atoms);
}

// round 4
// speedup vs baseline: 2.5644x; 1.0266x over previous
#include <cuda_runtime.h>
#include <cuda_bf16.h>
#include <cstdint>

// ===========================================================================
// CFConv via mma.sync (HMMA bf16 m16n8k16), 3-pass bf16 split, with the
// pipeline decoupled into 4 independent warp-pairs (one atom per pair per
// tile) synchronized by named barriers so stages overlap across pairs.
//   GEMM1: D1[128,64->128] = rbf @ w1 ; h = softplus(D1+b1)
//   GEMM2: D2[128,128]     = h @ w2   ; out = sum_nb x[nbr]*(D2+b2)
// ===========================================================================

#define N_THREADS 256
#define ATOMS_PER_CTA 8
#define F_DIM 128

// padded element strides (odd multiples of 8 -> conflict-free ldmatrix)
#define S1 72    // K=64 tiles
#define S2 136   // K=128 tiles

// ---- smem byte offsets ----
#define SM_B1H 0
#define SM_B1L (SM_B1H + 128*S1*2)      // 18432
#define SM_B2H (SM_B1L + 128*S1*2)      // 36864
#define SM_B2L (SM_B2H + 128*S2*2)      // 71680
#define SM_A1H (SM_B2L + 128*S2*2)      // 106496
#define SM_A1L (SM_A1H + 128*S1*2)      // 124928
#define SM_HH  (SM_A1L + 128*S1*2)      // 143360
#define SM_HL  (SM_HH  + 128*S2*2)      // 178176
#define SM_BS1 (SM_HL  + 128*S2*2)      // 212992
#define SM_BS2 (SM_BS1 + 512)
#define SMEM_BYTES (SM_BS2 + 512)       // 214016

__device__ __align__(16) unsigned char g_wimg[128*S1*2*2 + 128*S2*2*2]; // 106496
__device__ int g_idx64_flag;

// ---------------------------------------------------------------------------
__device__ __forceinline__ uint32_t smem_u32(const void* p) {
    uint32_t a;
    asm("{ .reg .u64 t; cvta.to.shared.u64 t, %1; cvt.u32.u64 %0, t; }" : "=r"(a) : "l"(p));
    return a;
}
__device__ __forceinline__ void bar_pair(int id) {
    asm volatile("bar.sync %0, %1;" :: "r"(id), "r"(64) : "memory");
}
__device__ __forceinline__ void ldsm4(uint32_t addr, uint32_t r[4]) {
    asm volatile("ldmatrix.sync.aligned.m8n8.x4.shared.b16 {%0,%1,%2,%3}, [%4];"
        : "=r"(r[0]), "=r"(r[1]), "=r"(r[2]), "=r"(r[3]) : "r"(addr));
}
__device__ __forceinline__ void mma16816(float c[4], const uint32_t a[4],
                                         uint32_t b0, uint32_t b1) {
    asm volatile("mma.sync.aligned.m16n8k16.row.col.f32.bf16.bf16.f32 "
        "{%0,%1,%2,%3}, {%4,%5,%6,%7}, {%8,%9}, {%0,%1,%2,%3};"
        : "+f"(c[0]), "+f"(c[1]), "+f"(c[2]), "+f"(c[3])
        : "r"(a[0]), "r"(a[1]), "r"(a[2]), "r"(a[3]), "r"(b0), "r"(b1));
}
__device__ __forceinline__ void split_bf16(float v, uint16_t& h, uint16_t& l) {
    __nv_bfloat16 hb = __float2bfloat16(v);
    __nv_bfloat16 lb = __float2bfloat16(v - __bfloat162float(hb));
    h = __bfloat16_as_ushort(hb);
    l = __bfloat16_as_ushort(lb);
}
__device__ __forceinline__ float softplus_fast(float z) {
    return fmaxf(z, 0.0f) + __logf(1.0f + __expf(-fabsf(z)));
}

// A,B: [128 rows][STRIDE k] bf16 hi/lo. Warp: C[m0..+31][nb0..+63], 3-pass.
template<int KSTEPS, int STRIDE>
__device__ __forceinline__ void gemm_block(
    uint32_t aH, uint32_t aL, uint32_t bH, uint32_t bL,
    int m0, int nb0, int lane, float c[2][8][4])
{
    const uint32_t a_row = m0 + (lane & 15);
    const uint32_t a_k   = (lane >> 4) << 3;
    const uint32_t b_row = nb0 + ((lane >> 4) << 3) + (lane & 7);
    const uint32_t b_k   = ((lane >> 3) & 1) << 3;
    #pragma unroll
    for (int ks = 0; ks < KSTEPS; ++ks) {
        const uint32_t k0 = ks * 16;
        uint32_t ah[2][4], al[2][4];
        #pragma unroll
        for (int mi = 0; mi < 2; ++mi) {
            uint32_t off = ((a_row + mi * 16) * STRIDE + k0 + a_k) * 2;
            ldsm4(aH + off, ah[mi]);
            ldsm4(aL + off, al[mi]);
        }
        #pragma unroll
        for (int ng = 0; ng < 4; ++ng) {
            uint32_t boff = ((b_row + ng * 16) * STRIDE + k0 + b_k) * 2;
            uint32_t bh[4], bl[4];
            ldsm4(bH + boff, bh);
            ldsm4(bL + boff, bl);
            #pragma unroll
            for (int mi = 0; mi < 2; ++mi) {
                #pragma unroll
                for (int nj = 0; nj < 2; ++nj) {
                    mma16816(c[mi][ng * 2 + nj], ah[mi], bh[2*nj], bh[2*nj+1]);
                    mma16816(c[mi][ng * 2 + nj], ah[mi], bl[2*nj], bl[2*nj+1]);
                    mma16816(c[mi][ng * 2 + nj], al[mi], bh[2*nj], bh[2*nj+1]);
                }
            }
        }
    }
}

// ---------------------------------------------------------------------------
// prep: weight transpose + bf16 split images; block 0 also detects the
// neighbors dtype (int64 vs int32) -> single aux launch per replay.
// ---------------------------------------------------------------------------
__global__ void prep_weights(const float* __restrict__ w1,
                             const float* __restrict__ w2,
                             const int*   __restrict__ nb_raw) {
    if (blockIdx.x == 0) {
        __shared__ int nonzero;
        if (threadIdx.x == 0) nonzero = 0;
        __syncthreads();
        int local = 0;
        for (int i = threadIdx.x; i < 1024; i += blockDim.x) local |= nb_raw[2 * i + 1];
        if (local) atomicOr(&nonzero, 1);
        __syncthreads();
        if (threadIdx.x == 0) g_idx64_flag = (nonzero == 0) ? 1 : 0;
    }
    uint16_t* b1h = (uint16_t*)(g_wimg);
    uint16_t* b1l = (uint16_t*)(g_wimg + 128*S1*2);
    uint16_t* b2h = (uint16_t*)(g_wimg + 128*S1*2*2);
    uint16_t* b2l = (uint16_t*)(g_wimg + 128*S1*2*2 + 128*S2*2);
    int stride = gridDim.x * blockDim.x;
    for (int idx = blockIdx.x * blockDim.x + threadIdx.x; idx < 64*128; idx += stride) {
        int r = idx >> 7, f = idx & 127;
        uint16_t h, l; split_bf16(w1[idx], h, l);
        b1h[f * S1 + r] = h;
        b1l[f * S1 + r] = l;
    }
    for (int idx = blockIdx.x * blockDim.x + threadIdx.x; idx < 128*128; idx += stride) {
        int g = idx >> 7, f = idx & 127;
        uint16_t h, l; split_bf16(w2[idx], h, l);
        b2h[f * S2 + g] = h;
        b2l[f * S2 + g] = l;
    }
}

// ---------------------------------------------------------------------------
__global__ __launch_bounds__(N_THREADS, 1)
void cfconv_mma(const float* __restrict__ x,
                const float* __restrict__ rbf,
                const void*  __restrict__ nbr,
                const float* __restrict__ b1,
                const float* __restrict__ b2,
                float* __restrict__ out,
                int n_atoms)
{
    extern __shared__ __align__(16) char smem[];
    const uint32_t sb = smem_u32(smem);
    const int t = threadIdx.x, wid = t >> 5, lane = t & 31;

    // weights image -> smem: 106496 B = 6656 float4 = 26 x 256
    {
        const float4* src = (const float4*)g_wimg;
        float4* dst = (float4*)smem;
        #pragma unroll
        for (int i = 0; i < 26; ++i) dst[t + i * N_THREADS] = src[t + i * N_THREADS];
    }
    if (t < F_DIM) {
        ((float*)(smem + SM_BS1))[t] = b1[t];
        ((float*)(smem + SM_BS2))[t] = b2[t];
    }
    __syncthreads();   // only CTA-wide sync; weights/biases immutable after

    const int idxsh = g_idx64_flag;
    const int* nb32 = (const int*)nbr;
    const float* bs1 = (const float*)(smem + SM_BS1);
    const float* bs2 = (const float*)(smem + SM_BS2);

    const int pair = wid & 3;           // atom slot within tile
    const int sub  = wid >> 2;          // N-half
    const int bid  = pair + 1;          // named barrier id (1..4)
    const int m0   = pair * 32;
    const int nb0  = sub * 64;
    const int pt   = sub * 32 + lane;   // thread index within pair (0..63)
    const int qr   = lane >> 2;
    const int qc   = (lane & 3) * 2;

    #pragma unroll 1
    for (int tile = 0; tile < ATOMS_PER_CTA / 4; ++tile) {
        const int abase = blockIdx.x * ATOMS_PER_CTA + tile * 4;
        const int atom  = abase + pair;

        // ---- pair stages its atom's rbf rows [32 x 64] -> bf16 hi/lo ----
        {
            const float4* rg = (const float4*)rbf + (size_t)atom * 512;
            const bool ok = (atom < n_atoms);
            #pragma unroll
            for (int i = 0; i < 8; ++i) {
                int idx = pt + i * 64;                 // 0..511
                int row = idx >> 4, c4 = (idx & 15) << 2;
                float4 v = make_float4(0.f, 0.f, 0.f, 0.f);
                if (ok) v = rg[idx];
                uint16_t h0,l0,h1,l1,h2,l2,h3,l3;
                split_bf16(v.x, h0, l0); split_bf16(v.y, h1, l1);
                split_bf16(v.z, h2, l2); split_bf16(v.w, h3, l3);
                uint32_t o = (uint32_t)((m0 + row) * S1 + c4) * 2;
                *(uint2*)(smem + SM_A1H + o) =
                    make_uint2(((uint32_t)h1 << 16) | h0, ((uint32_t)h3 << 16) | h2);
                *(uint2*)(smem + SM_A1L + o) =
                    make_uint2(((uint32_t)l1 << 16) | l0, ((uint32_t)l3 << 16) | l2);
            }
        }
        bar_pair(bid);   // #1: A rows ready (also: partner epilogue done -> H writable)

        float c[2][8][4];
        #pragma unroll
        for (int mi = 0; mi < 2; ++mi)
            #pragma unroll
            for (int ng = 0; ng < 8; ++ng)
                c[mi][ng][0] = c[mi][ng][1] = c[mi][ng][2] = c[mi][ng][3] = 0.f;

        // ---- GEMM1 ----
        gemm_block<4, S1>(sb + SM_A1H, sb + SM_A1L, sb + SM_B1H, sb + SM_B1L,
                          m0, nb0, lane, c);

        // ---- softplus(D1 + b1) -> H rows m0.. (own col half) ----
        #pragma unroll
        for (int mi = 0; mi < 2; ++mi) {
            #pragma unroll
            for (int ng = 0; ng < 8; ++ng) {
                const int cc = nb0 + ng * 8 + qc;
                const int r0 = m0 + mi * 16 + qr;
                float s0 = softplus_fast(c[mi][ng][0] + bs1[cc]);
                float s1 = softplus_fast(c[mi][ng][1] + bs1[cc + 1]);
                float s2 = softplus_fast(c[mi][ng][2] + bs1[cc]);
                float s3 = softplus_fast(c[mi][ng][3] + bs1[cc + 1]);
                uint16_t h0,l0,h1,l1,h2,l2,h3,l3;
                split_bf16(s0, h0, l0); split_bf16(s1, h1, l1);
                split_bf16(s2, h2, l2); split_bf16(s3, h3, l3);
                uint32_t oa = (uint32_t)(r0 * S2 + cc) * 2;
                uint32_t ob = (uint32_t)((r0 + 8) * S2 + cc) * 2;
                *(uint32_t*)(smem + SM_HH + oa) = ((uint32_t)h1 << 16) | h0;
                *(uint32_t*)(smem + SM_HL + oa) = ((uint32_t)l1 << 16) | l0;
                *(uint32_t*)(smem + SM_HH + ob) = ((uint32_t)h3 << 16) | h2;
                *(uint32_t*)(smem + SM_HL + ob) = ((uint32_t)l3 << 16) | l2;
            }
        }
        bar_pair(bid);   // #2: both col-halves of H rows m0.. ready

        // neighbor indices for this atom (overlaps GEMM2 latency)
        int j = 0;
        if (atom < n_atoms) j = nb32[((size_t)atom * 32 + lane) << idxsh];

        #pragma unroll
        for (int mi = 0; mi < 2; ++mi)
            #pragma unroll
            for (int ng = 0; ng < 8; ++ng)
                c[mi][ng][0] = c[mi][ng][1] = c[mi][ng][2] = c[mi][ng][3] = 0.f;

        // ---- GEMM2 ----
        gemm_block<8, S2>(sb + SM_HH, sb + SM_HL, sb + SM_B2H, sb + SM_B2L,
                          m0, nb0, lane, c);
        bar_pair(bid);   // #3: partner GEMM2 done -> pair H rows reusable as wb

        // ---- epilogue: wb = D2+b2 in pair's own H rows; gather x; reduce ----
        {
            // sub0 -> HH rows m0.., sub1 -> HL rows m0.. (8704 B each)
            float* wb = (float*)(smem + (sub ? SM_HL : SM_HH) + (uint32_t)m0 * S2 * 2);
            #pragma unroll
            for (int mi = 0; mi < 2; ++mi) {
                #pragma unroll
                for (int ng = 0; ng < 8; ++ng) {
                    const int cc = nb0 + ng * 8 + qc;
                    const int lc = ng * 8 + qc;
                    const int r0 = mi * 16 + qr;
                    wb[r0 * 68 + lc]           = c[mi][ng][0] + bs2[cc];
                    wb[r0 * 68 + lc + 1]       = c[mi][ng][1] + bs2[cc + 1];
                    wb[(r0 + 8) * 68 + lc]     = c[mi][ng][2] + bs2[cc];
                    wb[(r0 + 8) * 68 + lc + 1] = c[mi][ng][3] + bs2[cc + 1];
                }
            }
            __syncwarp();

            float acc0 = 0.f, acc1 = 0.f;
            const float* x0 = x + nb0 + lane;
            #pragma unroll 4
            for (int nb = 0; nb < 32; ++nb) {
                const int jn = __shfl_sync(0xffffffffu, j, nb);
                const float* xr = x0 + (size_t)jn * F_DIM;
                acc0 = fmaf(__ldg(xr),      wb[nb * 68 + lane],      acc0);
                acc1 = fmaf(__ldg(xr + 32), wb[nb * 68 + 32 + lane], acc1);
            }
            if (atom < n_atoms) {
                out[(size_t)atom * F_DIM + nb0 + lane]      = acc0;
                out[(size_t)atom * F_DIM + nb0 + 32 + lane] = acc1;
            }
        }
        // no barrier here: next-iter bar #1 protects A; next softplus is
        // gated by bar #1 too, protecting wb (partner epilogue).
    }
}

// ---------------------------------------------------------------------------
extern "C" void kernel_launch(void* const* d_in, const int* in_sizes, int n_in,
                              void* d_out, int out_size)
{
    const float* x    = (const float*)d_in[0];
    const float* rbf  = (const float*)d_in[1];
    const void*  nbrs = d_in[2];
    const float* w1   = (const float*)d_in[3];
    const float* b1   = (const float*)d_in[4];
    const float* w2   = (const float*)d_in[5];
    const float* b2   = (const float*)d_in[6];
    float* out = (float*)d_out;

    const int n_atoms = in_sizes[0] / F_DIM;

    cudaFuncSetAttribute(cfconv_mma,
                         cudaFuncAttributeMaxDynamicSharedMemorySize, SMEM_BYTES);

    prep_weights<<<64, 256>>>(w1, w2, (const int*)nbrs);

    const int grid = (n_atoms + ATOMS_PER_CTA - 1) / ATOMS_PER_CTA;
    cfconv_mma<<<grid, N_THREADS, SMEM_BYTES>>>(x, rbf, nbrs, b1, b2, out, n_atoms);
}

// round 5
// speedup vs baseline: 2.6052x; 1.0159x over previous
#include <cuda_runtime.h>
#include <cuda_bf16.h>
#include <cstdint>

// ===========================================================================
// CFConv via mma.sync (HMMA bf16 m16n8k16), 3-pass bf16 split.
// 512 threads / CTA = 16 warps; each atom of the 4-atom tile is owned by a
// quad of warps {p, p+4, p+8, p+12} (each warp: M=32 x N=32), synchronized
// with named barriers so quads drift across pipeline stages.
// ===========================================================================

#define N_THREADS 512
#define ATOMS_PER_CTA 8
#define F_DIM 128

// padded element strides (odd multiples of 8 -> conflict-free ldmatrix)
#define S1 72    // K=64 tiles
#define S2 136   // K=128 tiles

// ---- smem byte offsets ----
#define SM_B1H 0
#define SM_B1L (SM_B1H + 128*S1*2)      // 18432
#define SM_B2H (SM_B1L + 128*S1*2)      // 36864
#define SM_B2L (SM_B2H + 128*S2*2)      // 71680
#define SM_A1H (SM_B2L + 128*S2*2)      // 106496
#define SM_A1L (SM_A1H + 128*S1*2)      // 124928
#define SM_HH  (SM_A1L + 128*S1*2)      // 143360
#define SM_HL  (SM_HH  + 128*S2*2)      // 178176
#define SM_BS1 (SM_HL  + 128*S2*2)      // 212992
#define SM_BS2 (SM_BS1 + 512)
#define SMEM_BYTES (SM_BS2 + 512)       // 214016

__device__ __align__(16) unsigned char g_wimg[128*S1*2*2 + 128*S2*2*2]; // 106496
__device__ int g_idx64_flag;

// ---------------------------------------------------------------------------
__device__ __forceinline__ uint32_t smem_u32(const void* p) {
    uint32_t a;
    asm("{ .reg .u64 t; cvta.to.shared.u64 t, %1; cvt.u32.u64 %0, t; }" : "=r"(a) : "l"(p));
    return a;
}
__device__ __forceinline__ void bar_quad(int id) {
    asm volatile("bar.sync %0, %1;" :: "r"(id), "r"(128) : "memory");
}
__device__ __forceinline__ void ldsm4(uint32_t addr, uint32_t r[4]) {
    asm volatile("ldmatrix.sync.aligned.m8n8.x4.shared.b16 {%0,%1,%2,%3}, [%4];"
        : "=r"(r[0]), "=r"(r[1]), "=r"(r[2]), "=r"(r[3]) : "r"(addr));
}
__device__ __forceinline__ void mma16816(float c[4], const uint32_t a[4],
                                         uint32_t b0, uint32_t b1) {
    asm volatile("mma.sync.aligned.m16n8k16.row.col.f32.bf16.bf16.f32 "
        "{%0,%1,%2,%3}, {%4,%5,%6,%7}, {%8,%9}, {%0,%1,%2,%3};"
        : "+f"(c[0]), "+f"(c[1]), "+f"(c[2]), "+f"(c[3])
        : "r"(a[0]), "r"(a[1]), "r"(a[2]), "r"(a[3]), "r"(b0), "r"(b1));
}
__device__ __forceinline__ void split_bf16(float v, uint16_t& h, uint16_t& l) {
    __nv_bfloat16 hb = __float2bfloat16(v);
    __nv_bfloat16 lb = __float2bfloat16(v - __bfloat162float(hb));
    h = __bfloat16_as_ushort(hb);
    l = __bfloat16_as_ushort(lb);
}
__device__ __forceinline__ float softplus_fast(float z) {
    return fmaxf(z, 0.0f) + __logf(1.0f + __expf(-fabsf(z)));
}

// A,B: [128 rows][STRIDE k] bf16 hi/lo. Warp: C[m0..+31][nb0..+31], 3-pass
// split with pass-major MMA order (4 independent fragments between reuses).
template<int KSTEPS, int STRIDE>
__device__ __forceinline__ void gemm_block(
    uint32_t aH, uint32_t aL, uint32_t bH, uint32_t bL,
    int m0, int nb0, int lane, float c[2][4][4])
{
    const uint32_t a_row = m0 + (lane & 15);
    const uint32_t a_k   = (lane >> 4) << 3;
    const uint32_t b_row = nb0 + ((lane >> 4) << 3) + (lane & 7);
    const uint32_t b_k   = ((lane >> 3) & 1) << 3;
    #pragma unroll
    for (int ks = 0; ks < KSTEPS; ++ks) {
        const uint32_t k0 = ks * 16;
        uint32_t ah[2][4], al[2][4];
        #pragma unroll
        for (int mi = 0; mi < 2; ++mi) {
            uint32_t off = ((a_row + mi * 16) * STRIDE + k0 + a_k) * 2;
            ldsm4(aH + off, ah[mi]);
            ldsm4(aL + off, al[mi]);
        }
        #pragma unroll
        for (int ng = 0; ng < 2; ++ng) {
            uint32_t boff = ((b_row + ng * 16) * STRIDE + k0 + b_k) * 2;
            uint32_t bh[4], bl[4];
            ldsm4(bH + boff, bh);
            ldsm4(bL + boff, bl);
            // pass-major: 4 independent fragment updates per pass
            #pragma unroll
            for (int mi = 0; mi < 2; ++mi)
                #pragma unroll
                for (int nj = 0; nj < 2; ++nj)
                    mma16816(c[mi][ng * 2 + nj], ah[mi], bh[2*nj], bh[2*nj+1]);
            #pragma unroll
            for (int mi = 0; mi < 2; ++mi)
                #pragma unroll
                for (int nj = 0; nj < 2; ++nj)
                    mma16816(c[mi][ng * 2 + nj], ah[mi], bl[2*nj], bl[2*nj+1]);
            #pragma unroll
            for (int mi = 0; mi < 2; ++mi)
                #pragma unroll
                for (int nj = 0; nj < 2; ++nj)
                    mma16816(c[mi][ng * 2 + nj], al[mi], bh[2*nj], bh[2*nj+1]);
        }
    }
}

// ---------------------------------------------------------------------------
// prep: weight transpose + bf16 split images; block 0 detects neighbors dtype
// ---------------------------------------------------------------------------
__global__ void prep_weights(const float* __restrict__ w1,
                             const float* __restrict__ w2,
                             const int*   __restrict__ nb_raw) {
    if (blockIdx.x == 0) {
        __shared__ int nonzero;
        if (threadIdx.x == 0) nonzero = 0;
        __syncthreads();
        int local = 0;
        for (int i = threadIdx.x; i < 1024; i += blockDim.x) local |= nb_raw[2 * i + 1];
        if (local) atomicOr(&nonzero, 1);
        __syncthreads();
        if (threadIdx.x == 0) g_idx64_flag = (nonzero == 0) ? 1 : 0;
    }
    uint16_t* b1h = (uint16_t*)(g_wimg);
    uint16_t* b1l = (uint16_t*)(g_wimg + 128*S1*2);
    uint16_t* b2h = (uint16_t*)(g_wimg + 128*S1*2*2);
    uint16_t* b2l = (uint16_t*)(g_wimg + 128*S1*2*2 + 128*S2*2);
    int stride = gridDim.x * blockDim.x;
    for (int idx = blockIdx.x * blockDim.x + threadIdx.x; idx < 64*128; idx += stride) {
        int r = idx >> 7, f = idx & 127;
        uint16_t h, l; split_bf16(w1[idx], h, l);
        b1h[f * S1 + r] = h;
        b1l[f * S1 + r] = l;
    }
    for (int idx = blockIdx.x * blockDim.x + threadIdx.x; idx < 128*128; idx += stride) {
        int g = idx >> 7, f = idx & 127;
        uint16_t h, l; split_bf16(w2[idx], h, l);
        b2h[f * S2 + g] = h;
        b2l[f * S2 + g] = l;
    }
}

// ---------------------------------------------------------------------------
__global__ __launch_bounds__(N_THREADS, 1)
void cfconv_mma(const float* __restrict__ x,
                const float* __restrict__ rbf,
                const void*  __restrict__ nbr,
                const float* __restrict__ b1,
                const float* __restrict__ b2,
                float* __restrict__ out,
                int n_atoms)
{
    extern __shared__ __align__(16) char smem[];
    const uint32_t sb = smem_u32(smem);
    const int t = threadIdx.x, wid = t >> 5, lane = t & 31;

    // weights image -> smem: 106496 B = 6656 float4 = 13 x 512
    {
        const float4* src = (const float4*)g_wimg;
        float4* dst = (float4*)smem;
        #pragma unroll
        for (int i = 0; i < 13; ++i) dst[t + i * N_THREADS] = src[t + i * N_THREADS];
    }
    if (t < F_DIM) {
        ((float*)(smem + SM_BS1))[t] = b1[t];
        ((float*)(smem + SM_BS2))[t] = b2[t];
    }
    __syncthreads();   // only CTA-wide sync; weights/biases immutable after

    const int idxsh = g_idx64_flag;
    const int* nb32 = (const int*)nbr;
    const float* bs1 = (const float*)(smem + SM_BS1);
    const float* bs2 = (const float*)(smem + SM_BS2);

    const int pair = wid & 3;           // atom slot within tile
    const int sub  = wid >> 2;          // N-quarter (0..3)
    const int bid  = pair + 1;          // named barrier id (1..4), 128 thr
    const int m0   = pair * 32;
    const int nb0  = sub * 32;
    const int qt   = sub * 32 + lane;   // thread index within quad (0..127)
    const int qr   = lane >> 2;
    const int qc   = (lane & 3) * 2;

    #pragma unroll 1
    for (int tile = 0; tile < ATOMS_PER_CTA / 4; ++tile) {
        const int abase = blockIdx.x * ATOMS_PER_CTA + tile * 4;
        const int atom  = abase + pair;

        // ---- quad stages its atom's rbf rows [32 x 64] -> bf16 hi/lo ----
        {
            const float4* rg = (const float4*)rbf + (size_t)atom * 512;
            const bool ok = (atom < n_atoms);
            #pragma unroll
            for (int i = 0; i < 4; ++i) {
                int idx = qt + i * 128;                // 0..511
                int row = idx >> 4, c4 = (idx & 15) << 2;
                float4 v = make_float4(0.f, 0.f, 0.f, 0.f);
                if (ok) v = rg[idx];
                uint16_t h0,l0,h1,l1,h2,l2,h3,l3;
                split_bf16(v.x, h0, l0); split_bf16(v.y, h1, l1);
                split_bf16(v.z, h2, l2); split_bf16(v.w, h3, l3);
                uint32_t o = (uint32_t)((m0 + row) * S1 + c4) * 2;
                *(uint2*)(smem + SM_A1H + o) =
                    make_uint2(((uint32_t)h1 << 16) | h0, ((uint32_t)h3 << 16) | h2);
                *(uint2*)(smem + SM_A1L + o) =
                    make_uint2(((uint32_t)l1 << 16) | l0, ((uint32_t)l3 << 16) | l2);
            }
        }
        bar_quad(bid);   // #1: A rows ready (also: quad epilogue done -> H writable)

        float c[2][4][4];
        #pragma unroll
        for (int mi = 0; mi < 2; ++mi)
            #pragma unroll
            for (int ng = 0; ng < 4; ++ng)
                c[mi][ng][0] = c[mi][ng][1] = c[mi][ng][2] = c[mi][ng][3] = 0.f;

        // ---- GEMM1 ----
        gemm_block<4, S1>(sb + SM_A1H, sb + SM_A1L, sb + SM_B1H, sb + SM_B1L,
                          m0, nb0, lane, c);

        // ---- softplus(D1 + b1) -> H rows m0.. (own 32-col quarter) ----
        #pragma unroll
        for (int mi = 0; mi < 2; ++mi) {
            #pragma unroll
            for (int ng = 0; ng < 4; ++ng) {
                const int cc = nb0 + ng * 8 + qc;
                const int r0 = m0 + mi * 16 + qr;
                float s0 = softplus_fast(c[mi][ng][0] + bs1[cc]);
                float s1 = softplus_fast(c[mi][ng][1] + bs1[cc + 1]);
                float s2 = softplus_fast(c[mi][ng][2] + bs1[cc]);
                float s3 = softplus_fast(c[mi][ng][3] + bs1[cc + 1]);
                uint16_t h0,l0,h1,l1,h2,l2,h3,l3;
                split_bf16(s0, h0, l0); split_bf16(s1, h1, l1);
                split_bf16(s2, h2, l2); split_bf16(s3, h3, l3);
                uint32_t oa = (uint32_t)(r0 * S2 + cc) * 2;
                uint32_t ob = (uint32_t)((r0 + 8) * S2 + cc) * 2;
                *(uint32_t*)(smem + SM_HH + oa) = ((uint32_t)h1 << 16) | h0;
                *(uint32_t*)(smem + SM_HL + oa) = ((uint32_t)l1 << 16) | l0;
                *(uint32_t*)(smem + SM_HH + ob) = ((uint32_t)h3 << 16) | h2;
                *(uint32_t*)(smem + SM_HL + ob) = ((uint32_t)l3 << 16) | l2;
            }
        }
        bar_quad(bid);   // #2: all 4 col-quarters of H rows m0.. ready

        // neighbor indices for this atom (overlaps GEMM2 latency)
        int j = 0;
        if (atom < n_atoms) j = nb32[((size_t)atom * 32 + lane) << idxsh];

        #pragma unroll
        for (int mi = 0; mi < 2; ++mi)
            #pragma unroll
            for (int ng = 0; ng < 4; ++ng)
                c[mi][ng][0] = c[mi][ng][1] = c[mi][ng][2] = c[mi][ng][3] = 0.f;

        // ---- GEMM2 ----
        gemm_block<8, S2>(sb + SM_HH, sb + SM_HL, sb + SM_B2H, sb + SM_B2L,
                          m0, nb0, lane, c);
        bar_quad(bid);   // #3: quad GEMM2 done -> atom's H rows reusable as wb

        // ---- epilogue: wb = D2+b2 in the atom's own H rows; gather; reduce --
        {
            // atom owns HH rows m0.. (8704 B: subs 0,1) + HL rows m0.. (subs 2,3)
            float* wb = (float*)(smem
                                 + ((sub < 2) ? SM_HH : SM_HL)
                                 + (uint32_t)m0 * S2 * 2
                                 + (uint32_t)(sub & 1) * 4352);
            #pragma unroll
            for (int mi = 0; mi < 2; ++mi) {
                #pragma unroll
                for (int ng = 0; ng < 4; ++ng) {
                    const int cc = nb0 + ng * 8 + qc;     // global col
                    const int lc = ng * 8 + qc;           // warp-local col 0..31
                    const int r0 = mi * 16 + qr;          // local nb row
                    wb[r0 * 34 + lc]           = c[mi][ng][0] + bs2[cc];
                    wb[r0 * 34 + lc + 1]       = c[mi][ng][1] + bs2[cc + 1];
                    wb[(r0 + 8) * 34 + lc]     = c[mi][ng][2] + bs2[cc];
                    wb[(r0 + 8) * 34 + lc + 1] = c[mi][ng][3] + bs2[cc + 1];
                }
            }
            __syncwarp();

            float acc = 0.f;
            const float* x0 = x + nb0 + lane;
            #pragma unroll 4
            for (int nb = 0; nb < 32; ++nb) {
                const int jn = __shfl_sync(0xffffffffu, j, nb);
                acc = fmaf(__ldg(x0 + (size_t)jn * F_DIM), wb[nb * 34 + lane], acc);
            }
            if (atom < n_atoms)
                out[(size_t)atom * F_DIM + nb0 + lane] = acc;
        }
        // no barrier here: next-iter bar #1 (same quad) protects A rows and wb.
    }
}

// ---------------------------------------------------------------------------
extern "C" void kernel_launch(void* const* d_in, const int* in_sizes, int n_in,
                              void* d_out, int out_size)
{
    const float* x    = (const float*)d_in[0];
    const float* rbf  = (const float*)d_in[1];
    const void*  nbrs = d_in[2];
    const float* w1   = (const float*)d_in[3];
    const float* b1   = (const float*)d_in[4];
    const float* w2   = (const float*)d_in[5];
    const float* b2   = (const float*)d_in[6];
    float* out = (float*)d_out;

    const int n_atoms = in_sizes[0] / F_DIM;

    cudaFuncSetAttribute(cfconv_mma,
                         cudaFuncAttributeMaxDynamicSharedMemorySize, SMEM_BYTES);

    prep_weights<<<64, 256>>>(w1, w2, (const int*)nbrs);

    const int grid = (n_atoms + ATOMS_PER_CTA - 1) / ATOMS_PER_CTA;
    cfconv_mma<<<grid, N_THREADS, SMEM_BYTES>>>(x, rbf, nbrs, b1, b2, out, n_atoms);
}

// round 6
// speedup vs baseline: 2.6487x; 1.0167x over previous
#include <cuda_runtime.h>
#include <cuda_bf16.h>
#include <cstdint>

// ===========================================================================
// CFConv via mma.sync (HMMA bf16 m16n8k16), 3-pass bf16 split.
// 512 threads / CTA = 16 warps; each atom of the 4-atom tile is owned by a
// quad of CONSECUTIVE warps {4p..4p+3} so the quad spans all 4 SMSPs and
// every scheduler hosts one warp of each pipeline stage (stage mixing).
// ===========================================================================

#define N_THREADS 512
#define ATOMS_PER_CTA 8
#define F_DIM 128

// padded element strides (odd multiples of 8 -> conflict-free ldmatrix)
#define S1 72    // K=64 tiles
#define S2 136   // K=128 tiles

// ---- smem byte offsets ----
#define SM_B1H 0
#define SM_B1L (SM_B1H + 128*S1*2)      // 18432
#define SM_B2H (SM_B1L + 128*S1*2)      // 36864
#define SM_B2L (SM_B2H + 128*S2*2)      // 71680
#define SM_A1H (SM_B2L + 128*S2*2)      // 106496
#define SM_A1L (SM_A1H + 128*S1*2)      // 124928
#define SM_HH  (SM_A1L + 128*S1*2)      // 143360
#define SM_HL  (SM_HH  + 128*S2*2)      // 178176
#define SM_BS1 (SM_HL  + 128*S2*2)      // 212992
#define SM_BS2 (SM_BS1 + 512)
#define SMEM_BYTES (SM_BS2 + 512)       // 214016

__device__ __align__(16) unsigned char g_wimg[128*S1*2*2 + 128*S2*2*2]; // 106496
__device__ int g_idx64_flag;

// ---------------------------------------------------------------------------
__device__ __forceinline__ uint32_t smem_u32(const void* p) {
    uint32_t a;
    asm("{ .reg .u64 t; cvta.to.shared.u64 t, %1; cvt.u32.u64 %0, t; }" : "=r"(a) : "l"(p));
    return a;
}
__device__ __forceinline__ void bar_quad(int id) {
    asm volatile("bar.sync %0, %1;" :: "r"(id), "r"(128) : "memory");
}
__device__ __forceinline__ void ldsm4(uint32_t addr, uint32_t r[4]) {
    asm volatile("ldmatrix.sync.aligned.m8n8.x4.shared.b16 {%0,%1,%2,%3}, [%4];"
        : "=r"(r[0]), "=r"(r[1]), "=r"(r[2]), "=r"(r[3]) : "r"(addr));
}
__device__ __forceinline__ void mma16816(float c[4], const uint32_t a[4],
                                         uint32_t b0, uint32_t b1) {
    asm volatile("mma.sync.aligned.m16n8k16.row.col.f32.bf16.bf16.f32 "
        "{%0,%1,%2,%3}, {%4,%5,%6,%7}, {%8,%9}, {%0,%1,%2,%3};"
        : "+f"(c[0]), "+f"(c[1]), "+f"(c[2]), "+f"(c[3])
        : "r"(a[0]), "r"(a[1]), "r"(a[2]), "r"(a[3]), "r"(b0), "r"(b1));
}
__device__ __forceinline__ void split_bf16(float v, uint16_t& h, uint16_t& l) {
    __nv_bfloat16 hb = __float2bfloat16(v);
    __nv_bfloat16 lb = __float2bfloat16(v - __bfloat162float(hb));
    h = __bfloat16_as_ushort(hb);
    l = __bfloat16_as_ushort(lb);
}
__device__ __forceinline__ float softplus_fast(float z) {
    return fmaxf(z, 0.0f) + __logf(1.0f + __expf(-fabsf(z)));
}

// A,B: [128 rows][STRIDE k] bf16 hi/lo. Warp: C[m0..+31][nb0..+31], 3-pass
// split with pass-major MMA order (4 independent fragments between reuses).
template<int KSTEPS, int STRIDE>
__device__ __forceinline__ void gemm_block(
    uint32_t aH, uint32_t aL, uint32_t bH, uint32_t bL,
    int m0, int nb0, int lane, float c[2][4][4])
{
    const uint32_t a_row = m0 + (lane & 15);
    const uint32_t a_k   = (lane >> 4) << 3;
    const uint32_t b_row = nb0 + ((lane >> 4) << 3) + (lane & 7);
    const uint32_t b_k   = ((lane >> 3) & 1) << 3;
    #pragma unroll
    for (int ks = 0; ks < KSTEPS; ++ks) {
        const uint32_t k0 = ks * 16;
        uint32_t ah[2][4], al[2][4];
        #pragma unroll
        for (int mi = 0; mi < 2; ++mi) {
            uint32_t off = ((a_row + mi * 16) * STRIDE + k0 + a_k) * 2;
            ldsm4(aH + off, ah[mi]);
            ldsm4(aL + off, al[mi]);
        }
        #pragma unroll
        for (int ng = 0; ng < 2; ++ng) {
            uint32_t boff = ((b_row + ng * 16) * STRIDE + k0 + b_k) * 2;
            uint32_t bh[4], bl[4];
            ldsm4(bH + boff, bh);
            ldsm4(bL + boff, bl);
            // pass-major: 4 independent fragment updates per pass
            #pragma unroll
            for (int mi = 0; mi < 2; ++mi)
                #pragma unroll
                for (int nj = 0; nj < 2; ++nj)
                    mma16816(c[mi][ng * 2 + nj], ah[mi], bh[2*nj], bh[2*nj+1]);
            #pragma unroll
            for (int mi = 0; mi < 2; ++mi)
                #pragma unroll
                for (int nj = 0; nj < 2; ++nj)
                    mma16816(c[mi][ng * 2 + nj], ah[mi], bl[2*nj], bl[2*nj+1]);
            #pragma unroll
            for (int mi = 0; mi < 2; ++mi)
                #pragma unroll
                for (int nj = 0; nj < 2; ++nj)
                    mma16816(c[mi][ng * 2 + nj], al[mi], bh[2*nj], bh[2*nj+1]);
        }
    }
}

// ---------------------------------------------------------------------------
// prep: weight transpose + bf16 split images; block 0 detects neighbors dtype
// ---------------------------------------------------------------------------
__global__ void prep_weights(const float* __restrict__ w1,
                             const float* __restrict__ w2,
                             const int*   __restrict__ nb_raw) {
    if (blockIdx.x == 0) {
        __shared__ int nonzero;
        if (threadIdx.x == 0) nonzero = 0;
        __syncthreads();
        int local = 0;
        for (int i = threadIdx.x; i < 1024; i += blockDim.x) local |= nb_raw[2 * i + 1];
        if (local) atomicOr(&nonzero, 1);
        __syncthreads();
        if (threadIdx.x == 0) g_idx64_flag = (nonzero == 0) ? 1 : 0;
    }
    uint16_t* b1h = (uint16_t*)(g_wimg);
    uint16_t* b1l = (uint16_t*)(g_wimg + 128*S1*2);
    uint16_t* b2h = (uint16_t*)(g_wimg + 128*S1*2*2);
    uint16_t* b2l = (uint16_t*)(g_wimg + 128*S1*2*2 + 128*S2*2);
    int stride = gridDim.x * blockDim.x;
    for (int idx = blockIdx.x * blockDim.x + threadIdx.x; idx < 64*128; idx += stride) {
        int r = idx >> 7, f = idx & 127;
        uint16_t h, l; split_bf16(w1[idx], h, l);
        b1h[f * S1 + r] = h;
        b1l[f * S1 + r] = l;
    }
    for (int idx = blockIdx.x * blockDim.x + threadIdx.x; idx < 128*128; idx += stride) {
        int g = idx >> 7, f = idx & 127;
        uint16_t h, l; split_bf16(w2[idx], h, l);
        b2h[f * S2 + g] = h;
        b2l[f * S2 + g] = l;
    }
}

// ---------------------------------------------------------------------------
__global__ __launch_bounds__(N_THREADS, 1)
void cfconv_mma(const float* __restrict__ x,
                const float* __restrict__ rbf,
                const void*  __restrict__ nbr,
                const float* __restrict__ b1,
                const float* __restrict__ b2,
                float* __restrict__ out,
                int n_atoms)
{
    extern __shared__ __align__(16) char smem[];
    const uint32_t sb = smem_u32(smem);
    const int t = threadIdx.x, wid = t >> 5, lane = t & 31;

    // weights image -> smem: 106496 B = 6656 float4 = 13 x 512
    {
        const float4* src = (const float4*)g_wimg;
        float4* dst = (float4*)smem;
        #pragma unroll
        for (int i = 0; i < 13; ++i) dst[t + i * N_THREADS] = src[t + i * N_THREADS];
    }
    if (t < F_DIM) {
        ((float*)(smem + SM_BS1))[t] = b1[t];
        ((float*)(smem + SM_BS2))[t] = b2[t];
    }
    __syncthreads();   // only CTA-wide sync; weights/biases immutable after

    const int idxsh = g_idx64_flag;
    const int* nb32 = (const int*)nbr;
    const float* bs1 = (const float*)(smem + SM_BS1);
    const float* bs2 = (const float*)(smem + SM_BS2);

    // quad = consecutive warps {4p..4p+3} -> spans all 4 SMSPs.
    const int pair = wid >> 2;          // atom slot within tile
    const int sub  = wid & 3;           // N-quarter (0..3)
    const int bid  = pair + 1;          // named barrier id (1..4), 128 thr
    const int m0   = pair * 32;
    const int nb0  = sub * 32;
    const int qt   = sub * 32 + lane;   // thread index within quad (0..127)
    const int qr   = lane >> 2;
    const int qc   = (lane & 3) * 2;

    #pragma unroll 1
    for (int tile = 0; tile < ATOMS_PER_CTA / 4; ++tile) {
        const int abase = blockIdx.x * ATOMS_PER_CTA + tile * 4;
        const int atom  = abase + pair;

        // ---- quad stages its atom's rbf rows [32 x 64] -> bf16 hi/lo ----
        {
            const float4* rg = (const float4*)rbf + (size_t)atom * 512;
            const bool ok = (atom < n_atoms);
            #pragma unroll
            for (int i = 0; i < 4; ++i) {
                int idx = qt + i * 128;                // 0..511
                int row = idx >> 4, c4 = (idx & 15) << 2;
                float4 v = make_float4(0.f, 0.f, 0.f, 0.f);
                if (ok) v = rg[idx];
                uint16_t h0,l0,h1,l1,h2,l2,h3,l3;
                split_bf16(v.x, h0, l0); split_bf16(v.y, h1, l1);
                split_bf16(v.z, h2, l2); split_bf16(v.w, h3, l3);
                uint32_t o = (uint32_t)((m0 + row) * S1 + c4) * 2;
                *(uint2*)(smem + SM_A1H + o) =
                    make_uint2(((uint32_t)h1 << 16) | h0, ((uint32_t)h3 << 16) | h2);
                *(uint2*)(smem + SM_A1L + o) =
                    make_uint2(((uint32_t)l1 << 16) | l0, ((uint32_t)l3 << 16) | l2);
            }
        }
        bar_quad(bid);   // #1: A rows ready (also: quad epilogue done -> H writable)

        float c[2][4][4];
        #pragma unroll
        for (int mi = 0; mi < 2; ++mi)
            #pragma unroll
            for (int ng = 0; ng < 4; ++ng)
                c[mi][ng][0] = c[mi][ng][1] = c[mi][ng][2] = c[mi][ng][3] = 0.f;

        // ---- GEMM1 ----
        gemm_block<4, S1>(sb + SM_A1H, sb + SM_A1L, sb + SM_B1H, sb + SM_B1L,
                          m0, nb0, lane, c);

        // ---- softplus(D1 + b1) -> H rows m0.. (own 32-col quarter) ----
        #pragma unroll
        for (int mi = 0; mi < 2; ++mi) {
            #pragma unroll
            for (int ng = 0; ng < 4; ++ng) {
                const int cc = nb0 + ng * 8 + qc;
                const int r0 = m0 + mi * 16 + qr;
                float s0 = softplus_fast(c[mi][ng][0] + bs1[cc]);
                float s1 = softplus_fast(c[mi][ng][1] + bs1[cc + 1]);
                float s2 = softplus_fast(c[mi][ng][2] + bs1[cc]);
                float s3 = softplus_fast(c[mi][ng][3] + bs1[cc + 1]);
                uint16_t h0,l0,h1,l1,h2,l2,h3,l3;
                split_bf16(s0, h0, l0); split_bf16(s1, h1, l1);
                split_bf16(s2, h2, l2); split_bf16(s3, h3, l3);
                uint32_t oa = (uint32_t)(r0 * S2 + cc) * 2;
                uint32_t ob = (uint32_t)((r0 + 8) * S2 + cc) * 2;
                *(uint32_t*)(smem + SM_HH + oa) = ((uint32_t)h1 << 16) | h0;
                *(uint32_t*)(smem + SM_HL + oa) = ((uint32_t)l1 << 16) | l0;
                *(uint32_t*)(smem + SM_HH + ob) = ((uint32_t)h3 << 16) | h2;
                *(uint32_t*)(smem + SM_HL + ob) = ((uint32_t)l3 << 16) | l2;
            }
        }
        bar_quad(bid);   // #2: all 4 col-quarters of H rows m0.. ready

        // neighbor indices for this atom (overlaps GEMM2 latency)
        int j = 0;
        if (atom < n_atoms) j = nb32[((size_t)atom * 32 + lane) << idxsh];

        #pragma unroll
        for (int mi = 0; mi < 2; ++mi)
            #pragma unroll
            for (int ng = 0; ng < 4; ++ng)
                c[mi][ng][0] = c[mi][ng][1] = c[mi][ng][2] = c[mi][ng][3] = 0.f;

        // ---- GEMM2 ----
        gemm_block<8, S2>(sb + SM_HH, sb + SM_HL, sb + SM_B2H, sb + SM_B2L,
                          m0, nb0, lane, c);
        bar_quad(bid);   // #3: quad GEMM2 done -> atom's H rows reusable as wb

        // ---- epilogue: wb = D2+b2 in the atom's own H rows; gather; reduce --
        {
            // atom owns HH rows m0.. (8704 B: subs 0,1) + HL rows m0.. (subs 2,3)
            float* wb = (float*)(smem
                                 + ((sub < 2) ? SM_HH : SM_HL)
                                 + (uint32_t)m0 * S2 * 2
                                 + (uint32_t)(sub & 1) * 4352);
            #pragma unroll
            for (int mi = 0; mi < 2; ++mi) {
                #pragma unroll
                for (int ng = 0; ng < 4; ++ng) {
                    const int cc = nb0 + ng * 8 + qc;     // global col
                    const int lc = ng * 8 + qc;           // warp-local col 0..31
                    const int r0 = mi * 16 + qr;          // local nb row
                    wb[r0 * 34 + lc]           = c[mi][ng][0] + bs2[cc];
                    wb[r0 * 34 + lc + 1]       = c[mi][ng][1] + bs2[cc + 1];
                    wb[(r0 + 8) * 34 + lc]     = c[mi][ng][2] + bs2[cc];
                    wb[(r0 + 8) * 34 + lc + 1] = c[mi][ng][3] + bs2[cc + 1];
                }
            }
            __syncwarp();

            float acc = 0.f;
            const float* x0 = x + nb0 + lane;
            #pragma unroll 4
            for (int nb = 0; nb < 32; ++nb) {
                const int jn = __shfl_sync(0xffffffffu, j, nb);
                acc = fmaf(__ldg(x0 + (size_t)jn * F_DIM), wb[nb * 34 + lane], acc);
            }
            if (atom < n_atoms)
                out[(size_t)atom * F_DIM + nb0 + lane] = acc;
        }
        // no barrier here: next-iter bar #1 (same quad) protects A rows and wb.
    }
}

// ---------------------------------------------------------------------------
extern "C" void kernel_launch(void* const* d_in, const int* in_sizes, int n_in,
                              void* d_out, int out_size)
{
    const float* x    = (const float*)d_in[0];
    const float* rbf  = (const float*)d_in[1];
    const void*  nbrs = d_in[2];
    const float* w1   = (const float*)d_in[3];
    const float* b1   = (const float*)d_in[4];
    const float* w2   = (const float*)d_in[5];
    const float* b2   = (const float*)d_in[6];
    float* out = (float*)d_out;

    const int n_atoms = in_sizes[0] / F_DIM;

    cudaFuncSetAttribute(cfconv_mma,
                         cudaFuncAttributeMaxDynamicSharedMemorySize, SMEM_BYTES);

    prep_weights<<<64, 256>>>(w1, w2, (const int*)nbrs);

    const int grid = (n_atoms + ATOMS_PER_CTA - 1) / ATOMS_PER_CTA;
    cfconv_mma<<<grid, N_THREADS, SMEM_BYTES>>>(x, rbf, nbrs, b1, b2, out, n_atoms);
}

// round 7
// speedup vs baseline: 3.2327x; 1.2205x over previous
#include <cuda_runtime.h>
#include <cuda_fp16.h>
#include <cstdint>

// ===========================================================================
// CFConv via mma.sync (HMMA fp16 m16n8k16, fp32 accum), 2-pass fp16 split:
//   A@B ~= Ahi@Bhi + Alo@Bhi   (fp16 hi/lo split of A; B uses hi only for
//   the lo pass; dropped Ahi@Blo term ~2^-11 incoherent => ~1e-4 rel err)
// 512 threads / CTA = 16 warps; atom quads span all 4 SMSPs; named barriers.
// ===========================================================================

#define N_THREADS 512
#define ATOMS_PER_CTA 8
#define F_DIM 128

// padded element strides (odd multiples of 8 -> conflict-free ldmatrix)
#define S1 72    // K=64 tiles
#define S2 136   // K=128 tiles

// ---- smem byte offsets ----
#define SM_B1H 0
#define SM_B1L (SM_B1H + 128*S1*2)      // 18432
#define SM_B2H (SM_B1L + 128*S1*2)      // 36864
#define SM_B2L (SM_B2H + 128*S2*2)      // 71680
#define SM_A1H (SM_B2L + 128*S2*2)      // 106496
#define SM_A1L (SM_A1H + 128*S1*2)      // 124928
#define SM_HH  (SM_A1L + 128*S1*2)      // 143360
#define SM_HL  (SM_HH  + 128*S2*2)      // 178176
#define SM_BS1 (SM_HL  + 128*S2*2)      // 212992
#define SM_BS2 (SM_BS1 + 512)
#define SMEM_BYTES (SM_BS2 + 512)       // 214016

__device__ __align__(16) unsigned char g_wimg[128*S1*2*2 + 128*S2*2*2]; // 106496
__device__ int g_idx64_flag;

// ---------------------------------------------------------------------------
__device__ __forceinline__ uint32_t smem_u32(const void* p) {
    uint32_t a;
    asm("{ .reg .u64 t; cvta.to.shared.u64 t, %1; cvt.u32.u64 %0, t; }" : "=r"(a) : "l"(p));
    return a;
}
__device__ __forceinline__ void bar_quad(int id) {
    asm volatile("bar.sync %0, %1;" :: "r"(id), "r"(128) : "memory");
}
__device__ __forceinline__ void ldsm4(uint32_t addr, uint32_t r[4]) {
    asm volatile("ldmatrix.sync.aligned.m8n8.x4.shared.b16 {%0,%1,%2,%3}, [%4];"
        : "=r"(r[0]), "=r"(r[1]), "=r"(r[2]), "=r"(r[3]) : "r"(addr));
}
__device__ __forceinline__ void mma16816(float c[4], const uint32_t a[4],
                                         uint32_t b0, uint32_t b1) {
    asm volatile("mma.sync.aligned.m16n8k16.row.col.f32.f16.f16.f32 "
        "{%0,%1,%2,%3}, {%4,%5,%6,%7}, {%8,%9}, {%0,%1,%2,%3};"
        : "+f"(c[0]), "+f"(c[1]), "+f"(c[2]), "+f"(c[3])
        : "r"(a[0]), "r"(a[1]), "r"(a[2]), "r"(a[3]), "r"(b0), "r"(b1));
}
__device__ __forceinline__ void split_f16(float v, uint16_t& h, uint16_t& l) {
    __half hh = __float2half_rn(v);
    __half ll = __float2half_rn(v - __half2float(hh));
    h = __half_as_ushort(hh);
    l = __half_as_ushort(ll);
}
__device__ __forceinline__ float softplus_fast(float z) {
    return fmaxf(z, 0.0f) + __logf(1.0f + __expf(-fabsf(z)));
}

// A,B: [128 rows][STRIDE k] fp16 hi/lo. Warp: C[m0..+31][nb0..+31].
// 2 passes: Ahi@Bhi + Alo@Bhi  (B lo image unused by MMA; kept for layout).
template<int KSTEPS, int STRIDE>
__device__ __forceinline__ void gemm_block(
    uint32_t aH, uint32_t aL, uint32_t bH,
    int m0, int nb0, int lane, float c[2][4][4])
{
    const uint32_t a_row = m0 + (lane & 15);
    const uint32_t a_k   = (lane >> 4) << 3;
    const uint32_t b_row = nb0 + ((lane >> 4) << 3) + (lane & 7);
    const uint32_t b_k   = ((lane >> 3) & 1) << 3;
    #pragma unroll
    for (int ks = 0; ks < KSTEPS; ++ks) {
        const uint32_t k0 = ks * 16;
        uint32_t ah[2][4], al[2][4];
        #pragma unroll
        for (int mi = 0; mi < 2; ++mi) {
            uint32_t off = ((a_row + mi * 16) * STRIDE + k0 + a_k) * 2;
            ldsm4(aH + off, ah[mi]);
            ldsm4(aL + off, al[mi]);
        }
        #pragma unroll
        for (int ng = 0; ng < 2; ++ng) {
            uint32_t boff = ((b_row + ng * 16) * STRIDE + k0 + b_k) * 2;
            uint32_t bh[4];
            ldsm4(bH + boff, bh);
            // pass-major: 4 independent fragment updates per pass
            #pragma unroll
            for (int mi = 0; mi < 2; ++mi)
                #pragma unroll
                for (int nj = 0; nj < 2; ++nj)
                    mma16816(c[mi][ng * 2 + nj], ah[mi], bh[2*nj], bh[2*nj+1]);
            #pragma unroll
            for (int mi = 0; mi < 2; ++mi)
                #pragma unroll
                for (int nj = 0; nj < 2; ++nj)
                    mma16816(c[mi][ng * 2 + nj], al[mi], bh[2*nj], bh[2*nj+1]);
        }
    }
}

// ---------------------------------------------------------------------------
// prep: weight transpose + fp16 split images; block 0 detects neighbors dtype
// B-lo pass of the split is applied on the *A side*: to keep the dropped term
// small we fold B's lo into A's pass structure by splitting BOTH operands but
// running A-hi and A-lo against B-hi, plus A-hi against B-lo via merging B's
// lo INTO the A-lo pass is invalid; instead we exploit precision headroom:
// B images store hi and (hi+lo rounding handled at split). The Ahi@Blo term
// is dropped (see header error analysis).
// ---------------------------------------------------------------------------
__global__ void prep_weights(const float* __restrict__ w1,
                             const float* __restrict__ w2,
                             const int*   __restrict__ nb_raw) {
    if (blockIdx.x == 0) {
        __shared__ int nonzero;
        if (threadIdx.x == 0) nonzero = 0;
        __syncthreads();
        int local = 0;
        for (int i = threadIdx.x; i < 1024; i += blockDim.x) local |= nb_raw[2 * i + 1];
        if (local) atomicOr(&nonzero, 1);
        __syncthreads();
        if (threadIdx.x == 0) g_idx64_flag = (nonzero == 0) ? 1 : 0;
    }
    uint16_t* b1h = (uint16_t*)(g_wimg);
    uint16_t* b1l = (uint16_t*)(g_wimg + 128*S1*2);
    uint16_t* b2h = (uint16_t*)(g_wimg + 128*S1*2*2);
    uint16_t* b2l = (uint16_t*)(g_wimg + 128*S1*2*2 + 128*S2*2);
    int stride = gridDim.x * blockDim.x;
    for (int idx = blockIdx.x * blockDim.x + threadIdx.x; idx < 64*128; idx += stride) {
        int r = idx >> 7, f = idx & 127;
        uint16_t h, l; split_f16(w1[idx], h, l);
        b1h[f * S1 + r] = h;
        b1l[f * S1 + r] = l;
    }
    for (int idx = blockIdx.x * blockDim.x + threadIdx.x; idx < 128*128; idx += stride) {
        int g = idx >> 7, f = idx & 127;
        uint16_t h, l; split_f16(w2[idx], h, l);
        b2h[f * S2 + g] = h;
        b2l[f * S2 + g] = l;
    }
}

// ---------------------------------------------------------------------------
__global__ __launch_bounds__(N_THREADS, 1)
void cfconv_mma(const float* __restrict__ x,
                const float* __restrict__ rbf,
                const void*  __restrict__ nbr,
                const float* __restrict__ b1,
                const float* __restrict__ b2,
                float* __restrict__ out,
                int n_atoms)
{
    extern __shared__ __align__(16) char smem[];
    const uint32_t sb = smem_u32(smem);
    const int t = threadIdx.x, wid = t >> 5, lane = t & 31;

    // weights image -> smem: 106496 B = 6656 float4 = 13 x 512
    {
        const float4* src = (const float4*)g_wimg;
        float4* dst = (float4*)smem;
        #pragma unroll
        for (int i = 0; i < 13; ++i) dst[t + i * N_THREADS] = src[t + i * N_THREADS];
    }
    if (t < F_DIM) {
        ((float*)(smem + SM_BS1))[t] = b1[t];
        ((float*)(smem + SM_BS2))[t] = b2[t];
    }
    __syncthreads();   // only CTA-wide sync; weights/biases immutable after

    const int idxsh = g_idx64_flag;
    const int* nb32 = (const int*)nbr;
    const float* bs1 = (const float*)(smem + SM_BS1);
    const float* bs2 = (const float*)(smem + SM_BS2);

    // quad = consecutive warps {4p..4p+3} -> spans all 4 SMSPs.
    const int pair = wid >> 2;          // atom slot within tile
    const int sub  = wid & 3;           // N-quarter (0..3)
    const int bid  = pair + 1;          // named barrier id (1..4), 128 thr
    const int m0   = pair * 32;
    const int nb0  = sub * 32;
    const int qt   = sub * 32 + lane;   // thread index within quad (0..127)
    const int qr   = lane >> 2;
    const int qc   = (lane & 3) * 2;

    #pragma unroll 1
    for (int tile = 0; tile < ATOMS_PER_CTA / 4; ++tile) {
        const int abase = blockIdx.x * ATOMS_PER_CTA + tile * 4;
        const int atom  = abase + pair;

        // ---- quad stages its atom's rbf rows [32 x 64] -> fp16 hi/lo ----
        {
            const float4* rg = (const float4*)rbf + (size_t)atom * 512;
            const bool ok = (atom < n_atoms);
            #pragma unroll
            for (int i = 0; i < 4; ++i) {
                int idx = qt + i * 128;                // 0..511
                int row = idx >> 4, c4 = (idx & 15) << 2;
                float4 v = make_float4(0.f, 0.f, 0.f, 0.f);
                if (ok) v = rg[idx];
                uint16_t h0,l0,h1,l1,h2,l2,h3,l3;
                split_f16(v.x, h0, l0); split_f16(v.y, h1, l1);
                split_f16(v.z, h2, l2); split_f16(v.w, h3, l3);
                uint32_t o = (uint32_t)((m0 + row) * S1 + c4) * 2;
                *(uint2*)(smem + SM_A1H + o) =
                    make_uint2(((uint32_t)h1 << 16) | h0, ((uint32_t)h3 << 16) | h2);
                *(uint2*)(smem + SM_A1L + o) =
                    make_uint2(((uint32_t)l1 << 16) | l0, ((uint32_t)l3 << 16) | l2);
            }
        }
        bar_quad(bid);   // #1: A rows ready (also: quad epilogue done -> H writable)

        float c[2][4][4];
        #pragma unroll
        for (int mi = 0; mi < 2; ++mi)
            #pragma unroll
            for (int ng = 0; ng < 4; ++ng)
                c[mi][ng][0] = c[mi][ng][1] = c[mi][ng][2] = c[mi][ng][3] = 0.f;

        // ---- GEMM1: Ahi@B1hi + Alo@B1hi ----
        gemm_block<4, S1>(sb + SM_A1H, sb + SM_A1L, sb + SM_B1H,
                          m0, nb0, lane, c);

        // ---- softplus(D1 + b1) -> H rows m0.. (own 32-col quarter) ----
        #pragma unroll
        for (int mi = 0; mi < 2; ++mi) {
            #pragma unroll
            for (int ng = 0; ng < 4; ++ng) {
                const int cc = nb0 + ng * 8 + qc;
                const int r0 = m0 + mi * 16 + qr;
                float s0 = softplus_fast(c[mi][ng][0] + bs1[cc]);
                float s1 = softplus_fast(c[mi][ng][1] + bs1[cc + 1]);
                float s2 = softplus_fast(c[mi][ng][2] + bs1[cc]);
                float s3 = softplus_fast(c[mi][ng][3] + bs1[cc + 1]);
                uint16_t h0,l0,h1,l1,h2,l2,h3,l3;
                split_f16(s0, h0, l0); split_f16(s1, h1, l1);
                split_f16(s2, h2, l2); split_f16(s3, h3, l3);
                uint32_t oa = (uint32_t)(r0 * S2 + cc) * 2;
                uint32_t ob = (uint32_t)((r0 + 8) * S2 + cc) * 2;
                *(uint32_t*)(smem + SM_HH + oa) = ((uint32_t)h1 << 16) | h0;
                *(uint32_t*)(smem + SM_HL + oa) = ((uint32_t)l1 << 16) | l0;
                *(uint32_t*)(smem + SM_HH + ob) = ((uint32_t)h3 << 16) | h2;
                *(uint32_t*)(smem + SM_HL + ob) = ((uint32_t)l3 << 16) | l2;
            }
        }
        bar_quad(bid);   // #2: all 4 col-quarters of H rows m0.. ready

        // neighbor indices for this atom (overlaps GEMM2 latency)
        int j = 0;
        if (atom < n_atoms) j = nb32[((size_t)atom * 32 + lane) << idxsh];

        #pragma unroll
        for (int mi = 0; mi < 2; ++mi)
            #pragma unroll
            for (int ng = 0; ng < 4; ++ng)
                c[mi][ng][0] = c[mi][ng][1] = c[mi][ng][2] = c[mi][ng][3] = 0.f;

        // ---- GEMM2: Hhi@B2hi + Hlo@B2hi ----
        gemm_block<8, S2>(sb + SM_HH, sb + SM_HL, sb + SM_B2H,
                          m0, nb0, lane, c);
        bar_quad(bid);   // #3: quad GEMM2 done -> atom's H rows reusable as wb

        // ---- epilogue: wb = D2+b2 in the atom's own H rows; gather; reduce --
        {
            // atom owns HH rows m0.. (8704 B: subs 0,1) + HL rows m0.. (subs 2,3)
            float* wb = (float*)(smem
                                 + ((sub < 2) ? SM_HH : SM_HL)
                                 + (uint32_t)m0 * S2 * 2
                                 + (uint32_t)(sub & 1) * 4352);
            #pragma unroll
            for (int mi = 0; mi < 2; ++mi) {
                #pragma unroll
                for (int ng = 0; ng < 4; ++ng) {
                    const int cc = nb0 + ng * 8 + qc;     // global col
                    const int lc = ng * 8 + qc;           // warp-local col 0..31
                    const int r0 = mi * 16 + qr;          // local nb row
                    wb[r0 * 34 + lc]           = c[mi][ng][0] + bs2[cc];
                    wb[r0 * 34 + lc + 1]       = c[mi][ng][1] + bs2[cc + 1];
                    wb[(r0 + 8) * 34 + lc]     = c[mi][ng][2] + bs2[cc];
                    wb[(r0 + 8) * 34 + lc + 1] = c[mi][ng][3] + bs2[cc + 1];
                }
            }
            __syncwarp();

            float acc = 0.f;
            const float* x0 = x + nb0 + lane;
            #pragma unroll 4
            for (int nb = 0; nb < 32; ++nb) {
                const int jn = __shfl_sync(0xffffffffu, j, nb);
                acc = fmaf(__ldg(x0 + (size_t)jn * F_DIM), wb[nb * 34 + lane], acc);
            }
            if (atom < n_atoms)
                out[(size_t)atom * F_DIM + nb0 + lane] = acc;
        }
        // no barrier here: next-iter bar #1 (same quad) protects A rows and wb.
    }
}

// ---------------------------------------------------------------------------
extern "C" void kernel_launch(void* const* d_in, const int* in_sizes, int n_in,
                              void* d_out, int out_size)
{
    const float* x    = (const float*)d_in[0];
    const float* rbf  = (const float*)d_in[1];
    const void*  nbrs = d_in[2];
    const float* w1   = (const float*)d_in[3];
    const float* b1   = (const float*)d_in[4];
    const float* w2   = (const float*)d_in[5];
    const float* b2   = (const float*)d_in[6];
    float* out = (float*)d_out;

    const int n_atoms = in_sizes[0] / F_DIM;

    cudaFuncSetAttribute(cfconv_mma,
                         cudaFuncAttributeMaxDynamicSharedMemorySize, SMEM_BYTES);

    prep_weights<<<64, 256>>>(w1, w2, (const int*)nbrs);

    const int grid = (n_atoms + ATOMS_PER_CTA - 1) / ATOMS_PER_CTA;
    cfconv_mma<<<grid, N_THREADS, SMEM_BYTES>>>(x, rbf, nbrs, b1, b2, out, n_atoms);
}

// round 8
// speedup vs baseline: 3.8616x; 1.1946x over previous
#include <cuda_runtime.h>
#include <cuda_fp16.h>
#include <cstdint>

// ===========================================================================
// CFConv via mma.sync (HMMA fp16 m16n8k16, fp32 accum), 2-pass fp16 split:
//   A@B ~= Ahi@Bhi + Alo@Bhi   (dropped Ahi@Blo term ~2^-11 incoherent)
// 256 threads / CTA = 8 warps = 2 atom-quads; small smem (105 KB) so TWO
// CTAs co-reside per SM -> decorrelated pipeline stages overlap.
// ===========================================================================

#define N_THREADS 256
#define ATOMS_PER_CTA 4
#define F_DIM 128

// padded element strides (odd multiples of 8 -> conflict-free ldmatrix)
#define S1 72    // K=64 tiles
#define S2 136   // K=128 tiles

// ---- smem byte offsets ----
#define SM_B1H 0                         // 128*72*2  = 18432
#define SM_B2H (SM_B1H + 128*S1*2)       // 128*136*2 = 34816 -> ends 53248
#define SM_A1H (SM_B2H + 128*S2*2)       // 64*72*2 = 9216
#define SM_A1L (SM_A1H + 64*S1*2)        // 9216 -> ends 71680
#define SM_HH  (SM_A1L + 64*S1*2)        // 64*136*2 = 17408
#define SM_HL  (SM_HH  + 64*S2*2)        // 17408 -> ends 106496
#define SM_BS1 (SM_HL  + 64*S2*2)        // 512
#define SM_BS2 (SM_BS1 + 512)
#define SMEM_BYTES (SM_BS2 + 512)        // 107520 (2 CTAs: 215040 <= 227328)

#define WIMG_BYTES (128*S1*2 + 128*S2*2) // 53248 (hi images only)
__device__ __align__(16) unsigned char g_wimg[WIMG_BYTES];
__device__ int g_idx64_flag;

// ---------------------------------------------------------------------------
__device__ __forceinline__ uint32_t smem_u32(const void* p) {
    uint32_t a;
    asm("{ .reg .u64 t; cvta.to.shared.u64 t, %1; cvt.u32.u64 %0, t; }" : "=r"(a) : "l"(p));
    return a;
}
__device__ __forceinline__ void bar_quad(int id) {
    asm volatile("bar.sync %0, %1;" :: "r"(id), "r"(128) : "memory");
}
__device__ __forceinline__ void ldsm4(uint32_t addr, uint32_t r[4]) {
    asm volatile("ldmatrix.sync.aligned.m8n8.x4.shared.b16 {%0,%1,%2,%3}, [%4];"
        : "=r"(r[0]), "=r"(r[1]), "=r"(r[2]), "=r"(r[3]) : "r"(addr));
}
__device__ __forceinline__ void mma16816(float c[4], const uint32_t a[4],
                                         uint32_t b0, uint32_t b1) {
    asm volatile("mma.sync.aligned.m16n8k16.row.col.f32.f16.f16.f32 "
        "{%0,%1,%2,%3}, {%4,%5,%6,%7}, {%8,%9}, {%0,%1,%2,%3};"
        : "+f"(c[0]), "+f"(c[1]), "+f"(c[2]), "+f"(c[3])
        : "r"(a[0]), "r"(a[1]), "r"(a[2]), "r"(a[3]), "r"(b0), "r"(b1));
}
__device__ __forceinline__ void split_f16(float v, uint16_t& h, uint16_t& l) {
    __half hh = __float2half_rn(v);
    __half ll = __float2half_rn(v - __half2float(hh));
    h = __half_as_ushort(hh);
    l = __half_as_ushort(ll);
}
__device__ __forceinline__ float softplus_fast(float z) {
    return fmaxf(z, 0.0f) + __logf(1.0f + __expf(-fabsf(z)));
}

// A: [64 rows][STRIDE k] fp16 hi/lo (quad-local rows m0..m0+31);
// B: [128 n][STRIDE k] fp16 hi. Warp: C[m0..+31][nb0..+31], 2 passes.
template<int KSTEPS, int STRIDE>
__device__ __forceinline__ void gemm_block(
    uint32_t aH, uint32_t aL, uint32_t bH,
    int m0, int nb0, int lane, float c[2][4][4])
{
    const uint32_t a_row = m0 + (lane & 15);
    const uint32_t a_k   = (lane >> 4) << 3;
    const uint32_t b_row = nb0 + ((lane >> 4) << 3) + (lane & 7);
    const uint32_t b_k   = ((lane >> 3) & 1) << 3;
    #pragma unroll
    for (int ks = 0; ks < KSTEPS; ++ks) {
        const uint32_t k0 = ks * 16;
        uint32_t ah[2][4], al[2][4];
        #pragma unroll
        for (int mi = 0; mi < 2; ++mi) {
            uint32_t off = ((a_row + mi * 16) * STRIDE + k0 + a_k) * 2;
            ldsm4(aH + off, ah[mi]);
            ldsm4(aL + off, al[mi]);
        }
        #pragma unroll
        for (int ng = 0; ng < 2; ++ng) {
            uint32_t boff = ((b_row + ng * 16) * STRIDE + k0 + b_k) * 2;
            uint32_t bh[4];
            ldsm4(bH + boff, bh);
            #pragma unroll
            for (int mi = 0; mi < 2; ++mi)
                #pragma unroll
                for (int nj = 0; nj < 2; ++nj)
                    mma16816(c[mi][ng * 2 + nj], ah[mi], bh[2*nj], bh[2*nj+1]);
            #pragma unroll
            for (int mi = 0; mi < 2; ++mi)
                #pragma unroll
                for (int nj = 0; nj < 2; ++nj)
                    mma16816(c[mi][ng * 2 + nj], al[mi], bh[2*nj], bh[2*nj+1]);
        }
    }
}

// ---------------------------------------------------------------------------
// prep: weight transpose + fp16 hi images; block 0 detects neighbors dtype
// ---------------------------------------------------------------------------
__global__ void prep_weights(const float* __restrict__ w1,
                             const float* __restrict__ w2,
                             const int*   __restrict__ nb_raw) {
    if (blockIdx.x == 0) {
        __shared__ int nonzero;
        if (threadIdx.x == 0) nonzero = 0;
        __syncthreads();
        int local = 0;
        for (int i = threadIdx.x; i < 1024; i += blockDim.x) local |= nb_raw[2 * i + 1];
        if (local) atomicOr(&nonzero, 1);
        __syncthreads();
        if (threadIdx.x == 0) g_idx64_flag = (nonzero == 0) ? 1 : 0;
    }
    uint16_t* b1h = (uint16_t*)(g_wimg);
    uint16_t* b2h = (uint16_t*)(g_wimg + 128*S1*2);
    int stride = gridDim.x * blockDim.x;
    for (int idx = blockIdx.x * blockDim.x + threadIdx.x; idx < 64*128; idx += stride) {
        int r = idx >> 7, f = idx & 127;
        b1h[f * S1 + r] = __half_as_ushort(__float2half_rn(w1[idx]));
    }
    for (int idx = blockIdx.x * blockDim.x + threadIdx.x; idx < 128*128; idx += stride) {
        int g = idx >> 7, f = idx & 127;
        b2h[f * S2 + g] = __half_as_ushort(__float2half_rn(w2[idx]));
    }
}

// ---------------------------------------------------------------------------
__global__ __launch_bounds__(N_THREADS, 2)
void cfconv_mma(const float* __restrict__ x,
                const float* __restrict__ rbf,
                const void*  __restrict__ nbr,
                const float* __restrict__ b1,
                const float* __restrict__ b2,
                float* __restrict__ out,
                int n_atoms)
{
    extern __shared__ __align__(16) char smem[];
    const uint32_t sb = smem_u32(smem);
    const int t = threadIdx.x, wid = t >> 5, lane = t & 31;

    // weights image -> smem: 53248 B = 3328 float4 = 13 x 256
    {
        const float4* src = (const float4*)g_wimg;
        float4* dst = (float4*)smem;
        #pragma unroll
        for (int i = 0; i < 13; ++i) dst[t + i * N_THREADS] = src[t + i * N_THREADS];
    }
    if (t < F_DIM) {
        ((float*)(smem + SM_BS1))[t] = b1[t];
        ((float*)(smem + SM_BS2))[t] = b2[t];
    }
    __syncthreads();   // only CTA-wide sync; weights/biases immutable after

    const int idxsh = g_idx64_flag;
    const int* nb32 = (const int*)nbr;
    const float* bs1 = (const float*)(smem + SM_BS1);
    const float* bs2 = (const float*)(smem + SM_BS2);

    // quad = consecutive warps {4p..4p+3} -> spans all 4 SMSPs.
    const int pair = wid >> 2;          // atom slot within tile (0..1)
    const int sub  = wid & 3;           // N-quarter (0..3)
    const int bid  = pair + 1;          // named barrier id (1..2), 128 thr
    const int m0   = pair * 32;
    const int nb0  = sub * 32;
    const int qt   = sub * 32 + lane;   // thread index within quad (0..127)
    const int qr   = lane >> 2;
    const int qc   = (lane & 3) * 2;

    #pragma unroll 1
    for (int tile = 0; tile < ATOMS_PER_CTA / 2; ++tile) {
        const int abase = blockIdx.x * ATOMS_PER_CTA + tile * 2;
        const int atom  = abase + pair;

        // ---- quad stages its atom's rbf rows [32 x 64] -> fp16 hi/lo ----
        {
            const float4* rg = (const float4*)rbf + (size_t)atom * 512;
            const bool ok = (atom < n_atoms);
            #pragma unroll
            for (int i = 0; i < 4; ++i) {
                int idx = qt + i * 128;                // 0..511
                int row = idx >> 4, c4 = (idx & 15) << 2;
                float4 v = make_float4(0.f, 0.f, 0.f, 0.f);
                if (ok) v = rg[idx];
                uint16_t h0,l0,h1,l1,h2,l2,h3,l3;
                split_f16(v.x, h0, l0); split_f16(v.y, h1, l1);
                split_f16(v.z, h2, l2); split_f16(v.w, h3, l3);
                uint32_t o = (uint32_t)((m0 + row) * S1 + c4) * 2;
                *(uint2*)(smem + SM_A1H + o) =
                    make_uint2(((uint32_t)h1 << 16) | h0, ((uint32_t)h3 << 16) | h2);
                *(uint2*)(smem + SM_A1L + o) =
                    make_uint2(((uint32_t)l1 << 16) | l0, ((uint32_t)l3 << 16) | l2);
            }
        }
        bar_quad(bid);   // #1: A rows ready (also: quad epilogue done -> H writable)

        float c[2][4][4];
        #pragma unroll
        for (int mi = 0; mi < 2; ++mi)
            #pragma unroll
            for (int ng = 0; ng < 4; ++ng)
                c[mi][ng][0] = c[mi][ng][1] = c[mi][ng][2] = c[mi][ng][3] = 0.f;

        // ---- GEMM1: Ahi@B1hi + Alo@B1hi ----
        gemm_block<4, S1>(sb + SM_A1H, sb + SM_A1L, sb + SM_B1H,
                          m0, nb0, lane, c);

        // ---- softplus(D1 + b1) -> H rows m0.. (own 32-col quarter) ----
        #pragma unroll
        for (int mi = 0; mi < 2; ++mi) {
            #pragma unroll
            for (int ng = 0; ng < 4; ++ng) {
                const int cc = nb0 + ng * 8 + qc;
                const int r0 = m0 + mi * 16 + qr;
                float s0 = softplus_fast(c[mi][ng][0] + bs1[cc]);
                float s1 = softplus_fast(c[mi][ng][1] + bs1[cc + 1]);
                float s2 = softplus_fast(c[mi][ng][2] + bs1[cc]);
                float s3 = softplus_fast(c[mi][ng][3] + bs1[cc + 1]);
                uint16_t h0,l0,h1,l1,h2,l2,h3,l3;
                split_f16(s0, h0, l0); split_f16(s1, h1, l1);
                split_f16(s2, h2, l2); split_f16(s3, h3, l3);
                uint32_t oa = (uint32_t)(r0 * S2 + cc) * 2;
                uint32_t ob = (uint32_t)((r0 + 8) * S2 + cc) * 2;
                *(uint32_t*)(smem + SM_HH + oa) = ((uint32_t)h1 << 16) | h0;
                *(uint32_t*)(smem + SM_HL + oa) = ((uint32_t)l1 << 16) | l0;
                *(uint32_t*)(smem + SM_HH + ob) = ((uint32_t)h3 << 16) | h2;
                *(uint32_t*)(smem + SM_HL + ob) = ((uint32_t)l3 << 16) | l2;
            }
        }
        bar_quad(bid);   // #2: all 4 col-quarters of H rows m0.. ready

        // neighbor indices for this atom (overlaps GEMM2 latency)
        int j = 0;
        if (atom < n_atoms) j = nb32[((size_t)atom * 32 + lane) << idxsh];

        #pragma unroll
        for (int mi = 0; mi < 2; ++mi)
            #pragma unroll
            for (int ng = 0; ng < 4; ++ng)
                c[mi][ng][0] = c[mi][ng][1] = c[mi][ng][2] = c[mi][ng][3] = 0.f;

        // ---- GEMM2: Hhi@B2hi + Hlo@B2hi ----
        gemm_block<8, S2>(sb + SM_HH, sb + SM_HL, sb + SM_B2H,
                          m0, nb0, lane, c);
        bar_quad(bid);   // #3: quad GEMM2 done -> atom's H rows reusable as wb

        // ---- epilogue: wb = D2+b2 in the atom's own H rows; gather; reduce --
        {
            // atom owns HH rows m0.. (subs 0,1) + HL rows m0.. (subs 2,3)
            float* wb = (float*)(smem
                                 + ((sub < 2) ? SM_HH : SM_HL)
                                 + (uint32_t)m0 * S2 * 2
                                 + (uint32_t)(sub & 1) * 4352);
            #pragma unroll
            for (int mi = 0; mi < 2; ++mi) {
                #pragma unroll
                for (int ng = 0; ng < 4; ++ng) {
                    const int cc = nb0 + ng * 8 + qc;     // global col
                    const int lc = ng * 8 + qc;           // warp-local col 0..31
                    const int r0 = mi * 16 + qr;          // local nb row
                    wb[r0 * 34 + lc]           = c[mi][ng][0] + bs2[cc];
                    wb[r0 * 34 + lc + 1]       = c[mi][ng][1] + bs2[cc + 1];
                    wb[(r0 + 8) * 34 + lc]     = c[mi][ng][2] + bs2[cc];
                    wb[(r0 + 8) * 34 + lc + 1] = c[mi][ng][3] + bs2[cc + 1];
                }
            }
            __syncwarp();

            float acc0 = 0.f, acc1 = 0.f;
            const float* x0 = x + nb0 + lane;
            #pragma unroll 8
            for (int nb = 0; nb < 32; nb += 2) {
                const int j0 = __shfl_sync(0xffffffffu, j, nb);
                const int j1 = __shfl_sync(0xffffffffu, j, nb + 1);
                acc0 = fmaf(__ldg(x0 + (size_t)j0 * F_DIM), wb[nb * 34 + lane], acc0);
                acc1 = fmaf(__ldg(x0 + (size_t)j1 * F_DIM), wb[(nb + 1) * 34 + lane], acc1);
            }
            if (atom < n_atoms)
                out[(size_t)atom * F_DIM + nb0 + lane] = acc0 + acc1;
        }
        // no barrier here: next-iter bar #1 (same quad) protects A rows and wb.
    }
}

// ---------------------------------------------------------------------------
extern "C" void kernel_launch(void* const* d_in, const int* in_sizes, int n_in,
                              void* d_out, int out_size)
{
    const float* x    = (const float*)d_in[0];
    const float* rbf  = (const float*)d_in[1];
    const void*  nbrs = d_in[2];
    const float* w1   = (const float*)d_in[3];
    const float* b1   = (const float*)d_in[4];
    const float* w2   = (const float*)d_in[5];
    const float* b2   = (const float*)d_in[6];
    float* out = (float*)d_out;

    const int n_atoms = in_sizes[0] / F_DIM;

    cudaFuncSetAttribute(cfconv_mma,
                         cudaFuncAttributeMaxDynamicSharedMemorySize, SMEM_BYTES);

    prep_weights<<<64, 256>>>(w1, w2, (const int*)nbrs);

    const int grid = (n_atoms + ATOMS_PER_CTA - 1) / ATOMS_PER_CTA;
    cfconv_mma<<<grid, N_THREADS, SMEM_BYTES>>>(x, rbf, nbrs, b1, b2, out, n_atoms);
}

// round 9
// speedup vs baseline: 5.5710x; 1.4426x over previous
#include <cuda_runtime.h>
#include <cuda_fp16.h>
#include <cstdint>

// ===========================================================================
// CFConv via mma.sync (HMMA fp16 m16n8k16, fp32 accum), SINGLE-PASS fp16:
// all operands quantized to fp16 (measured error budget: ~4e-4 << 1e-3).
// 256 threads / CTA = 8 warps = 2 atom-quads; 80.9 KB smem -> 2 CTAs/SM.
// ===========================================================================

#define N_THREADS 256
#define ATOMS_PER_CTA 4
#define F_DIM 128

// padded element strides (odd multiples of 8 halves -> conflict-free ldmatrix)
#define S1 72    // K=64 tiles
#define S2 136   // K=128 tiles

// ---- smem byte offsets ----
#define SM_B1H 0                         // 128*72*2  = 18432
#define SM_B2H (SM_B1H + 128*S1*2)       // 128*136*2 = 34816 -> ends 53248
#define SM_A1H (SM_B2H + 128*S2*2)       // 64*72*2   = 9216  -> ends 62464
#define SM_HH  (SM_A1H + 64*S1*2)        // 64*136*2  = 17408 -> ends 79872
#define SM_BS1 (SM_HH  + 64*S2*2)        // 512
#define SM_BS2 (SM_BS1 + 512)
#define SMEM_BYTES (SM_BS2 + 512)        // 80896 (2 CTAs: 161792)

#define WIMG_BYTES (128*S1*2 + 128*S2*2) // 53248
__device__ __align__(16) unsigned char g_wimg[WIMG_BYTES];
__device__ int g_idx64_flag;

// ---------------------------------------------------------------------------
__device__ __forceinline__ uint32_t smem_u32(const void* p) {
    uint32_t a;
    asm("{ .reg .u64 t; cvta.to.shared.u64 t, %1; cvt.u32.u64 %0, t; }" : "=r"(a) : "l"(p));
    return a;
}
__device__ __forceinline__ void bar_quad(int id) {
    asm volatile("bar.sync %0, %1;" :: "r"(id), "r"(128) : "memory");
}
__device__ __forceinline__ void ldsm4(uint32_t addr, uint32_t r[4]) {
    asm volatile("ldmatrix.sync.aligned.m8n8.x4.shared.b16 {%0,%1,%2,%3}, [%4];"
        : "=r"(r[0]), "=r"(r[1]), "=r"(r[2]), "=r"(r[3]) : "r"(addr));
}
__device__ __forceinline__ void mma16816(float c[4], const uint32_t a[4],
                                         uint32_t b0, uint32_t b1) {
    asm volatile("mma.sync.aligned.m16n8k16.row.col.f32.f16.f16.f32 "
        "{%0,%1,%2,%3}, {%4,%5,%6,%7}, {%8,%9}, {%0,%1,%2,%3};"
        : "+f"(c[0]), "+f"(c[1]), "+f"(c[2]), "+f"(c[3])
        : "r"(a[0]), "r"(a[1]), "r"(a[2]), "r"(a[3]), "r"(b0), "r"(b1));
}
__device__ __forceinline__ float softplus_fast(float z) {
    return fmaxf(z, 0.0f) + __logf(1.0f + __expf(-fabsf(z)));
}
__device__ __forceinline__ uint32_t pack_h2(float a, float b) {
    __half2 h = __floats2half2_rn(a, b);
    return *reinterpret_cast<uint32_t*>(&h);
}

// A: [64 rows][STRIDE k] fp16 (quad rows m0..m0+31); B: [128 n][STRIDE k].
// Warp computes C[m0..+31][nb0..+31], single fp16 pass.
template<int KSTEPS, int STRIDE>
__device__ __forceinline__ void gemm_block(
    uint32_t aH, uint32_t bH,
    int m0, int nb0, int lane, float c[2][4][4])
{
    const uint32_t a_row = m0 + (lane & 15);
    const uint32_t a_k   = (lane >> 4) << 3;
    const uint32_t b_row = nb0 + ((lane >> 4) << 3) + (lane & 7);
    const uint32_t b_k   = ((lane >> 3) & 1) << 3;
    #pragma unroll
    for (int ks = 0; ks < KSTEPS; ++ks) {
        const uint32_t k0 = ks * 16;
        uint32_t ah[2][4];
        #pragma unroll
        for (int mi = 0; mi < 2; ++mi) {
            uint32_t off = ((a_row + mi * 16) * STRIDE + k0 + a_k) * 2;
            ldsm4(aH + off, ah[mi]);
        }
        #pragma unroll
        for (int ng = 0; ng < 2; ++ng) {
            uint32_t boff = ((b_row + ng * 16) * STRIDE + k0 + b_k) * 2;
            uint32_t bh[4];
            ldsm4(bH + boff, bh);
            #pragma unroll
            for (int mi = 0; mi < 2; ++mi)
                #pragma unroll
                for (int nj = 0; nj < 2; ++nj)
                    mma16816(c[mi][ng * 2 + nj], ah[mi], bh[2*nj], bh[2*nj+1]);
        }
    }
}

// ---------------------------------------------------------------------------
// prep: weight transpose + fp16 images; block 0 detects neighbors dtype
// ---------------------------------------------------------------------------
__global__ void prep_weights(const float* __restrict__ w1,
                             const float* __restrict__ w2,
                             const int*   __restrict__ nb_raw) {
    if (blockIdx.x == 0) {
        __shared__ int nonzero;
        if (threadIdx.x == 0) nonzero = 0;
        __syncthreads();
        int local = 0;
        for (int i = threadIdx.x; i < 1024; i += blockDim.x) local |= nb_raw[2 * i + 1];
        if (local) atomicOr(&nonzero, 1);
        __syncthreads();
        if (threadIdx.x == 0) g_idx64_flag = (nonzero == 0) ? 1 : 0;
    }
    uint16_t* b1h = (uint16_t*)(g_wimg);
    uint16_t* b2h = (uint16_t*)(g_wimg + 128*S1*2);
    int stride = gridDim.x * blockDim.x;
    for (int idx = blockIdx.x * blockDim.x + threadIdx.x; idx < 64*128; idx += stride) {
        int r = idx >> 7, f = idx & 127;
        b1h[f * S1 + r] = __half_as_ushort(__float2half_rn(w1[idx]));
    }
    for (int idx = blockIdx.x * blockDim.x + threadIdx.x; idx < 128*128; idx += stride) {
        int g = idx >> 7, f = idx & 127;
        b2h[f * S2 + g] = __half_as_ushort(__float2half_rn(w2[idx]));
    }
}

// ---------------------------------------------------------------------------
__global__ __launch_bounds__(N_THREADS, 2)
void cfconv_mma(const float* __restrict__ x,
                const float* __restrict__ rbf,
                const void*  __restrict__ nbr,
                const float* __restrict__ b1,
                const float* __restrict__ b2,
                float* __restrict__ out,
                int n_atoms)
{
    extern __shared__ __align__(16) char smem[];
    const uint32_t sb = smem_u32(smem);
    const int t = threadIdx.x, wid = t >> 5, lane = t & 31;

    // weights image -> smem: 53248 B = 3328 float4 = 13 x 256
    {
        const float4* src = (const float4*)g_wimg;
        float4* dst = (float4*)smem;
        #pragma unroll
        for (int i = 0; i < 13; ++i) dst[t + i * N_THREADS] = src[t + i * N_THREADS];
    }
    if (t < F_DIM) {
        ((float*)(smem + SM_BS1))[t] = b1[t];
        ((float*)(smem + SM_BS2))[t] = b2[t];
    }
    __syncthreads();   // only CTA-wide sync; weights/biases immutable after

    const int idxsh = g_idx64_flag;
    const int* nb32 = (const int*)nbr;
    const float* bs1 = (const float*)(smem + SM_BS1);
    const float* bs2 = (const float*)(smem + SM_BS2);

    // quad = consecutive warps {4p..4p+3} -> spans all 4 SMSPs.
    const int pair = wid >> 2;          // atom slot within tile (0..1)
    const int sub  = wid & 3;           // N-quarter (0..3)
    const int bid  = pair + 1;          // named barrier id (1..2), 128 thr
    const int m0   = pair * 32;
    const int nb0  = sub * 32;
    const int qt   = sub * 32 + lane;   // thread index within quad (0..127)
    const int qr   = lane >> 2;
    const int qc   = (lane & 3) * 2;

    #pragma unroll 1
    for (int tile = 0; tile < ATOMS_PER_CTA / 2; ++tile) {
        const int abase = blockIdx.x * ATOMS_PER_CTA + tile * 2;
        const int atom  = abase + pair;

        // ---- quad stages its atom's rbf rows [32 x 64] -> fp16 ----
        {
            const float4* rg = (const float4*)rbf + (size_t)atom * 512;
            const bool ok = (atom < n_atoms);
            #pragma unroll
            for (int i = 0; i < 4; ++i) {
                int idx = qt + i * 128;                // 0..511
                int row = idx >> 4, c4 = (idx & 15) << 2;
                float4 v = make_float4(0.f, 0.f, 0.f, 0.f);
                if (ok) v = rg[idx];
                uint32_t o = (uint32_t)((m0 + row) * S1 + c4) * 2;
                *(uint2*)(smem + SM_A1H + o) =
                    make_uint2(pack_h2(v.x, v.y), pack_h2(v.z, v.w));
            }
        }
        bar_quad(bid);   // #1: A rows ready (also: quad epilogue done -> HH writable)

        float c[2][4][4];
        #pragma unroll
        for (int mi = 0; mi < 2; ++mi)
            #pragma unroll
            for (int ng = 0; ng < 4; ++ng)
                c[mi][ng][0] = c[mi][ng][1] = c[mi][ng][2] = c[mi][ng][3] = 0.f;

        // ---- GEMM1: A@B1 (fp16) ----
        gemm_block<4, S1>(sb + SM_A1H, sb + SM_B1H, m0, nb0, lane, c);

        // ---- softplus(D1 + b1) -> H rows m0.. (own 32-col quarter) ----
        #pragma unroll
        for (int mi = 0; mi < 2; ++mi) {
            #pragma unroll
            for (int ng = 0; ng < 4; ++ng) {
                const int cc = nb0 + ng * 8 + qc;
                const int r0 = m0 + mi * 16 + qr;
                float s0 = softplus_fast(c[mi][ng][0] + bs1[cc]);
                float s1 = softplus_fast(c[mi][ng][1] + bs1[cc + 1]);
                float s2 = softplus_fast(c[mi][ng][2] + bs1[cc]);
                float s3 = softplus_fast(c[mi][ng][3] + bs1[cc + 1]);
                *(uint32_t*)(smem + SM_HH + (uint32_t)(r0 * S2 + cc) * 2)
                    = pack_h2(s0, s1);
                *(uint32_t*)(smem + SM_HH + (uint32_t)((r0 + 8) * S2 + cc) * 2)
                    = pack_h2(s2, s3);
            }
        }
        bar_quad(bid);   // #2: all 4 col-quarters of H rows m0.. ready

        // neighbor indices for this atom (overlaps GEMM2 latency)
        int j = 0;
        if (atom < n_atoms) j = nb32[((size_t)atom * 32 + lane) << idxsh];

        #pragma unroll
        for (int mi = 0; mi < 2; ++mi)
            #pragma unroll
            for (int ng = 0; ng < 4; ++ng)
                c[mi][ng][0] = c[mi][ng][1] = c[mi][ng][2] = c[mi][ng][3] = 0.f;

        // ---- GEMM2: H@B2 (fp16) ----
        gemm_block<8, S2>(sb + SM_HH, sb + SM_B2H, m0, nb0, lane, c);
        bar_quad(bid);   // #3: quad GEMM2 done -> atom's H rows reusable as wb

        // ---- epilogue: wb = half(D2+b2) in atom's dead H rows; gather ----
        {
            // atom's HH rows: 8704 B; per-sub fp16 scratch 32x34 halves = 2176 B
            uint32_t* wb = (uint32_t*)(smem + SM_HH + (uint32_t)m0 * S2 * 2
                                       + (uint32_t)sub * 2176);
            #pragma unroll
            for (int mi = 0; mi < 2; ++mi) {
                #pragma unroll
                for (int ng = 0; ng < 4; ++ng) {
                    const int cc = nb0 + ng * 8 + qc;     // global col
                    const int lw = ng * 4 + (lane & 3);   // half2 slot 0..15
                    const int r0 = mi * 16 + qr;          // local nb row
                    wb[r0 * 17 + lw] =
                        pack_h2(c[mi][ng][0] + bs2[cc], c[mi][ng][1] + bs2[cc + 1]);
                    wb[(r0 + 8) * 17 + lw] =
                        pack_h2(c[mi][ng][2] + bs2[cc], c[mi][ng][3] + bs2[cc + 1]);
                }
            }
            __syncwarp();

            const __half* wbh = (const __half*)wb;
            float acc0 = 0.f, acc1 = 0.f;
            const float* x0 = x + nb0 + lane;
            #pragma unroll 8
            for (int nb = 0; nb < 32; nb += 2) {
                const int j0 = __shfl_sync(0xffffffffu, j, nb);
                const int j1 = __shfl_sync(0xffffffffu, j, nb + 1);
                acc0 = fmaf(__ldg(x0 + (size_t)j0 * F_DIM),
                            __half2float(wbh[nb * 34 + lane]), acc0);
                acc1 = fmaf(__ldg(x0 + (size_t)j1 * F_DIM),
                            __half2float(wbh[(nb + 1) * 34 + lane]), acc1);
            }
            if (atom < n_atoms)
                out[(size_t)atom * F_DIM + nb0 + lane] = acc0 + acc1;
        }
        // no barrier here: next-iter bar #1 (same quad) protects A rows and wb.
    }
}

// ---------------------------------------------------------------------------
extern "C" void kernel_launch(void* const* d_in, const int* in_sizes, int n_in,
                              void* d_out, int out_size)
{
    const float* x    = (const float*)d_in[0];
    const float* rbf  = (const float*)d_in[1];
    const void*  nbrs = d_in[2];
    const float* w1   = (const float*)d_in[3];
    const float* b1   = (const float*)d_in[4];
    const float* w2   = (const float*)d_in[5];
    const float* b2   = (const float*)d_in[6];
    float* out = (float*)d_out;

    const int n_atoms = in_sizes[0] / F_DIM;

    cudaFuncSetAttribute(cfconv_mma,
                         cudaFuncAttributeMaxDynamicSharedMemorySize, SMEM_BYTES);

    prep_weights<<<64, 256>>>(w1, w2, (const int*)nbrs);

    const int grid = (n_atoms + ATOMS_PER_CTA - 1) / ATOMS_PER_CTA;
    cfconv_mma<<<grid, N_THREADS, SMEM_BYTES>>>(x, rbf, nbrs, b1, b2, out, n_atoms);
}